// round 14
// baseline (speedup 1.0000x reference)
#include <cuda_runtime.h>
#include <cuda_bf16.h>
#include <cstdint>
#include <cstddef>

// Problem constants
#define BATCH   16
#define NTOK    577
#define CDIM    768
#define HEADS   12
#define DHEAD   64
#define MROWS   (BATCH * NTOK)          // 9232
#define QKVCOLS (3 * CDIM)              // 2304
#define BHTOT   (BATCH * HEADS)         // 192

// ===================== helpers ==============================================
__device__ __forceinline__ uint32_t smem_to_u32(const void* smem_ptr) {
    uint32_t addr;
    asm("{ .reg .u64 tmp; cvta.to.shared.u64 tmp, %1; cvt.u32.u64 %0, tmp; }"
        : "=r"(addr) : "l"(smem_ptr));
    return addr;
}

__device__ __forceinline__ void ldsm4(uint32_t* r, uint32_t addr) {
    asm volatile("ldmatrix.sync.aligned.m8n8.x4.shared.b16 {%0,%1,%2,%3}, [%4];"
                 : "=r"(r[0]), "=r"(r[1]), "=r"(r[2]), "=r"(r[3]) : "r"(addr));
}

__device__ __forceinline__ void ldsm4t(uint32_t* r, uint32_t addr) {
    asm volatile("ldmatrix.sync.aligned.m8n8.x4.trans.shared.b16 {%0,%1,%2,%3}, [%4];"
                 : "=r"(r[0]), "=r"(r[1]), "=r"(r[2]), "=r"(r[3]) : "r"(addr));
}

__device__ __forceinline__ void mma16816(float* c, const uint32_t* a,
                                         uint32_t b0, uint32_t b1) {
    asm volatile(
        "mma.sync.aligned.m16n8k16.row.col.f32.bf16.bf16.f32 "
        "{%0,%1,%2,%3}, {%4,%5,%6,%7}, {%8,%9}, {%0,%1,%2,%3};"
        : "+f"(c[0]), "+f"(c[1]), "+f"(c[2]), "+f"(c[3])
        : "r"(a[0]), "r"(a[1]), "r"(a[2]), "r"(a[3]), "r"(b0), "r"(b1));
}

// pack(lo, hi) -> bf16x2 register (lo in lower 16 bits)
__device__ __forceinline__ uint32_t pack_bf16x2(float lo, float hi) {
    uint32_t r;
    asm("cvt.rn.bf16x2.f32 %0, %1, %2;" : "=r"(r) : "f"(hi), "f"(lo));
    return r;
}

// 16B async copy; pred=false => zero-fill (reads 0 bytes)
__device__ __forceinline__ void cp_async16(uint32_t dst, const void* src, bool pred) {
    int sz = pred ? 16 : 0;
    asm volatile("cp.async.cg.shared.global [%0], [%1], 16, %2;"
                 :: "r"(dst), "l"(src), "r"(sz) : "memory");
}
__device__ __forceinline__ void cp_commit() {
    asm volatile("cp.async.commit_group;" ::: "memory");
}
template <int N>
__device__ __forceinline__ void cp_wait() {
    asm volatile("cp.async.wait_group %0;" :: "n"(N) : "memory");
}

// ---------------- scratch (no allocations allowed -> device globals) --------
// bf16 hi/lo split operands for tensor-core GEMMs
__device__ __nv_bfloat16 gAh[(size_t)MROWS * CDIM];           // x split
__device__ __nv_bfloat16 gAl[(size_t)MROWS * CDIM];
__device__ __nv_bfloat16 gCh[(size_t)MROWS * CDIM];           // attn-out split
__device__ __nv_bfloat16 gCl[(size_t)MROWS * CDIM];
__device__ __nv_bfloat16 gWqh[(size_t)QKVCOLS * CDIM];        // w_qkv^T split
__device__ __nv_bfloat16 gWql[(size_t)QKVCOLS * CDIM];
__device__ __nv_bfloat16 gWph[(size_t)CDIM * CDIM];           // w_proj^T split
__device__ __nv_bfloat16 gWpl[(size_t)CDIM * CDIM];

// bf16 hi/lo Q/K/V, (B*H, N, D)
__device__ __nv_bfloat16 gQh[(size_t)BHTOT * NTOK * DHEAD];
__device__ __nv_bfloat16 gQl[(size_t)BHTOT * NTOK * DHEAD];
__device__ __nv_bfloat16 gKh[(size_t)BHTOT * NTOK * DHEAD];
__device__ __nv_bfloat16 gKl[(size_t)BHTOT * NTOK * DHEAD];
__device__ __nv_bfloat16 gVh[(size_t)BHTOT * NTOK * DHEAD];
__device__ __nv_bfloat16 gVl[(size_t)BHTOT * NTOK * DHEAD];

// =============== fused operand prep (split x + transpose/split weights) =====
#define NB_X  ((MROWS * CDIM / 4 + 255) / 256)           // 6924
#define NB_WQ ((QKVCOLS / 32) * (CDIM / 32))             // 1728
#define NB_WP ((CDIM / 32) * (CDIM / 32))                // 576

__device__ __forceinline__ void wsplit_body(const float* __restrict__ w,
                                            __nv_bfloat16* __restrict__ oh,
                                            __nv_bfloat16* __restrict__ ol,
                                            int K, int N, int bx, int by,
                                            int tid, float (*t)[33]) {
    int n0 = bx * 32, k0 = by * 32;
    int tx = tid & 31, ty = tid >> 5;
#pragma unroll
    for (int j = 0; j < 32; j += 8)
        t[ty + j][tx] = w[(size_t)(k0 + ty + j) * N + n0 + tx];
    __syncthreads();
#pragma unroll
    for (int j = 0; j < 32; j += 8) {
        float v = t[tx][ty + j];
        int n = n0 + ty + j, k = k0 + tx;
        __nv_bfloat16 h = __float2bfloat16_rn(v);
        __nv_bfloat16 l = __float2bfloat16_rn(v - __bfloat162float(h));
        oh[(size_t)n * K + k] = h;
        ol[(size_t)n * K + k] = l;
    }
}

__global__ __launch_bounds__(256) void k_prep(const float* __restrict__ x,
                                              const float* __restrict__ w_qkv,
                                              const float* __restrict__ w_proj) {
    __shared__ float t[32][33];
    const int b = blockIdx.x;
    const int tid = threadIdx.x;
    if (b < NB_X) {
        int i = b * 256 + tid;
        const int n4 = MROWS * CDIM / 4;
        if (i < n4) {
            float4 v = ((const float4*)x)[i];
            float f[4] = {v.x, v.y, v.z, v.w};
            __align__(8) __nv_bfloat16 h[4];
            __align__(8) __nv_bfloat16 l[4];
#pragma unroll
            for (int j = 0; j < 4; j++) {
                h[j] = __float2bfloat16_rn(f[j]);
                l[j] = __float2bfloat16_rn(f[j] - __bfloat162float(h[j]));
            }
            *(uint2*)(gAh + 4 * (size_t)i) = *(uint2*)h;
            *(uint2*)(gAl + 4 * (size_t)i) = *(uint2*)l;
        }
    } else if (b < NB_X + NB_WQ) {
        int bb = b - NB_X;
        wsplit_body(w_qkv, gWqh, gWql, CDIM, QKVCOLS,
                    bb % (QKVCOLS / 32), bb / (QKVCOLS / 32), tid, t);
    } else {
        int bb = b - NB_X - NB_WQ;
        wsplit_body(w_proj, gWph, gWpl, CDIM, CDIM,
                    bb % (CDIM / 32), bb / (CDIM / 32), tid, t);
    }
}

// =================== HMMA bf16x3 GEMM: C = A@B + bias =======================
// Persistent CTAs; 3-stage cp.async pipeline; 2 CTAs/SM.
// Tile 128x128, BK=32, 8 warps (2x4).
// ROPE=true: qkv GEMM — epilogue applies RoPE + bf16 hi/lo split and scatters
// straight into gQ/gK/gV.
#define GT_TILE 8192                    // 128 x 32 bf16
#define GT_BUF  (4 * GT_TILE)           // 32KB / stage (Ah,Al,Bh,Bl)
#define GT_SMEM (3 * GT_BUF)            // 96KB, 3 stages

template <bool ROPE>
__global__ __launch_bounds__(256, 2) void k_gemm_mma(
    const __nv_bfloat16* __restrict__ Ah, const __nv_bfloat16* __restrict__ Al,
    const __nv_bfloat16* __restrict__ Bh, const __nv_bfloat16* __restrict__ Bl,
    const float* __restrict__ bias, float* __restrict__ C, int M, int N,
    const float* __restrict__ cosb, const float* __restrict__ sinb) {
    extern __shared__ __align__(128) char smem[];
    const uint32_t sbase = smem_to_u32(smem);

    const int tid  = threadIdx.x;
    const int lane = tid & 31;
    const int wid  = tid >> 5;
    const int wm   = wid >> 2;
    const int wn   = wid & 3;

    // global->smem chunk mapping (tile-invariant parts)
    const int u0 = tid, u1 = tid + 256;
    const int r0 = u0 >> 2, c0 = u0 & 3;
    const int r1 = u1 >> 2, c1 = u1 & 3;
    const uint32_t so0 = (uint32_t)(r0 * 64 + ((c0 ^ ((r0 >> 1) & 3)) << 4));
    const uint32_t so1 = (uint32_t)(r1 * 64 + ((c1 ^ ((r1 >> 1) & 3)) << 4));

    // ldmatrix source offsets (tile invariant)
    const int lrow = lane & 15;
    const int lkc  = lane >> 4;
    uint32_t offA[2][4], offB[2][2];
#pragma unroll
    for (int kk2 = 0; kk2 < 2; kk2++) {
        int cc = kk2 * 2 + lkc;
#pragma unroll
        for (int mi = 0; mi < 4; mi++) {
            int rr = wm * 64 + mi * 16 + lrow;
            offA[kk2][mi] = (uint32_t)(rr * 64 + ((cc ^ ((rr >> 1) & 3)) << 4));
        }
#pragma unroll
        for (int nb = 0; nb < 2; nb++) {
            int rr = wn * 32 + nb * 16 + lrow;
            offB[kk2][nb] = (uint32_t)(rr * 64 + ((cc ^ ((rr >> 1) & 3)) << 4));
        }
    }

    const int NSTAGE = CDIM / 32;        // 24
    const int ncols  = N / 128;
    const int nrows  = (M + 127) / 128;
    const int ntiles = ncols * nrows;

    for (int tile = blockIdx.x; tile < ntiles; tile += gridDim.x) {
        const int block_col = (tile % ncols) * 128;
        const int block_row = (tile / ncols) * 128;

        const bool a0ok = (block_row + r0) < M;
        const bool a1ok = (block_row + r1) < M;
        const int ar0 = a0ok ? (block_row + r0) : (M - 1);
        const int ar1 = a1ok ? (block_row + r1) : (M - 1);
        const size_t gA0 = (size_t)ar0 * CDIM + c0 * 8;
        const size_t gA1 = (size_t)ar1 * CDIM + c1 * 8;
        const size_t gB0 = (size_t)(block_col + r0) * CDIM + c0 * 8;
        const size_t gB1 = (size_t)(block_col + r1) * CDIM + c1 * 8;

        float acc[4][4][4];
#pragma unroll
        for (int mi = 0; mi < 4; mi++)
#pragma unroll
            for (int ni = 0; ni < 4; ni++)
#pragma unroll
                for (int j = 0; j < 4; j++) acc[mi][ni][j] = 0.f;

        auto issue = [&](int s, int buf) {
            const int ko = s * 32;
            const uint32_t b = sbase + (uint32_t)buf * GT_BUF;
            cp_async16(b + so0,               Ah + gA0 + ko, a0ok);
            cp_async16(b + so1,               Ah + gA1 + ko, a1ok);
            cp_async16(b + GT_TILE + so0,     Al + gA0 + ko, a0ok);
            cp_async16(b + GT_TILE + so1,     Al + gA1 + ko, a1ok);
            cp_async16(b + 2 * GT_TILE + so0, Bh + gB0 + ko, true);
            cp_async16(b + 2 * GT_TILE + so1, Bh + gB1 + ko, true);
            cp_async16(b + 3 * GT_TILE + so0, Bl + gB0 + ko, true);
            cp_async16(b + 3 * GT_TILE + so1, Bl + gB1 + ko, true);
        };

        // bufs 0/1 are free at tile entry (stages 21/22 of the previous tile
        // were fully consumed before its stage-23 barrier).
        issue(0, 0); cp_commit();
        issue(1, 1); cp_commit();

        int buf = 0;
        for (int s = 0; s < NSTAGE; s++) {
            if (s == NSTAGE - 1) cp_wait<0>();   // drain: newest group = stage s
            else                 cp_wait<1>();
            __syncthreads();

            if (s + 2 < NSTAGE) {
                issue(s + 2, (s + 2) % 3);
                cp_commit();
            }

            const uint32_t tbase = sbase + (uint32_t)buf * GT_BUF;
#pragma unroll
            for (int kk2 = 0; kk2 < 2; kk2++) {
                uint32_t ah[4][4], al[4][4];
#pragma unroll
                for (int mi = 0; mi < 4; mi++) {
                    ldsm4(ah[mi], tbase + offA[kk2][mi]);
                    ldsm4(al[mi], tbase + GT_TILE + offA[kk2][mi]);
                }
#pragma unroll
                for (int nb = 0; nb < 2; nb++) {
                    uint32_t bh[4], bl[4];
                    ldsm4(bh, tbase + 2 * GT_TILE + offB[kk2][nb]);
                    ldsm4(bl, tbase + 3 * GT_TILE + offB[kk2][nb]);
#pragma unroll
                    for (int mi = 0; mi < 4; mi++) {
#pragma unroll
                        for (int nsub = 0; nsub < 2; nsub++) {
                            const int ni = nb * 2 + nsub;
                            uint32_t b0 = bh[nsub], b1 = bh[nsub + 2];
                            uint32_t c0r = bl[nsub], c1r = bl[nsub + 2];
                            mma16816(acc[mi][ni], ah[mi], b0, b1);
                            mma16816(acc[mi][ni], ah[mi], c0r, c1r);
                            mma16816(acc[mi][ni], al[mi], b0, b1);
                        }
                    }
                }
            }
            buf = (buf + 1) % 3;
        }

        // ---- epilogue ----
        const int erow = lane >> 2;
        const int ecol = (lane & 3) << 1;

        if (!ROPE) {
#pragma unroll
            for (int mi = 0; mi < 4; mi++) {
#pragma unroll
                for (int ni = 0; ni < 4; ni++) {
                    int r = block_row + wm * 64 + mi * 16 + erow;
                    int col = block_col + wn * 32 + ni * 8 + ecol;
                    float2 bv = *(const float2*)(bias + col);
                    if (r < M) {
                        float2 o = make_float2(acc[mi][ni][0] + bv.x,
                                               acc[mi][ni][1] + bv.y);
                        *(float2*)(C + (size_t)r * N + col) = o;
                    }
                    if (r + 8 < M) {
                        float2 o = make_float2(acc[mi][ni][2] + bv.x,
                                               acc[mi][ni][3] + bv.y);
                        *(float2*)(C + (size_t)(r + 8) * N + col) = o;
                    }
                }
            }
        } else {
            // fused RoPE + bf16 hi/lo split + scatter to Q/K/V
            const int sec = block_col / CDIM;           // 0=Q,1=K,2=V
            const int hbase = (block_col % CDIM) / DHEAD;
            __nv_bfloat16* dh = sec == 0 ? gQh : (sec == 1 ? gKh : gVh);
            __nv_bfloat16* dl = sec == 0 ? gQl : (sec == 1 ? gKl : gVl);
#pragma unroll
            for (int mi = 0; mi < 4; mi++) {
#pragma unroll
                for (int rp = 0; rp < 2; rp++) {
                    int r = block_row + wm * 64 + mi * 16 + erow + rp * 8;
                    if (r >= M) continue;
                    int bidx = r / NTOK;
                    int n = r - bidx * NTOK;
#pragma unroll
                    for (int ni = 0; ni < 4; ni++) {
                        int lc = wn * 32 + ni * 8 + ecol;
                        int col = block_col + lc;
                        float v0 = acc[mi][ni][rp * 2 + 0] + bias[col];
                        float v1 = acc[mi][ni][rp * 2 + 1] + bias[col + 1];
                        int d = lc & 63;
                        int h = hbase + (lc >> 6);
                        if (sec < 2 && n > 0) {
                            float cc = cosb[(size_t)(n - 1) * 32 + (d >> 1)];
                            float ss = sinb[(size_t)(n - 1) * 32 + (d >> 1)];
                            float t0 = v0 * cc - v1 * ss;
                            float t1 = v0 * ss + v1 * cc;
                            v0 = t0; v1 = t1;
                        }
                        float h0 = __bfloat162float(__float2bfloat16_rn(v0));
                        float h1 = __bfloat162float(__float2bfloat16_rn(v1));
                        size_t o = ((size_t)(bidx * HEADS + h) * NTOK + n) * DHEAD + d;
                        *(uint32_t*)(dh + o) = pack_bf16x2(h0, h1);
                        *(uint32_t*)(dl + o) = pack_bf16x2(v0 - h0, v1 - h1);
                    }
                }
            }
        }
    }
}

// ============== Flash attention on HMMA, bf16x3, persistent CTAs ============
// 2-stage cp.async double buffer for K/V. smem 96KB; 2 CTAs/SM.
#define ASM_QH   0
#define ASM_QL   16384
#define ASM_KV0  32768
#define ASM_KVSZ 32768                 // KH+0, KL+8192, VH+16384, VL+24576
#define ASM_TOTAL 98304
#define QTILES   ((NTOK + 127) / 128)  // 5
#define ATILES   (QTILES * BHTOT)      // 960

__global__ __launch_bounds__(256, 2) void k_attn_mma() {
    extern __shared__ __align__(128) char asmem[];
    const uint32_t sb = smem_to_u32(asmem);
    const int tid = threadIdx.x;
    const int lane = tid & 31;
    const int wid = tid >> 5;

    const int m0 = wid * 16;
    const int alr = m0 + (lane & 15);
    const int akc = lane >> 4;
    uint32_t offQ[4];
#pragma unroll
    for (int k16 = 0; k16 < 4; k16++)
        offQ[k16] = (uint32_t)(alr * 128 + (((2 * k16 + akc) ^ (alr & 7)) << 4));

    const float scale = 0.125f;

    for (int tile = blockIdx.x; tile < ATILES; tile += gridDim.x) {
        const int q0 = (tile % QTILES) * 128;   // consecutive tiles share bh? no:
        const int bh = tile / QTILES;           // tiles of one bh land on
                                                // consecutive CTAs -> L2 share
        const size_t gbase = (size_t)bh * NTOK * DHEAD;

        __syncthreads();   // prior tile's compute done before Q overwrite

        // ---- load Q tile ----
#pragma unroll
        for (int i = 0; i < 4; i++) {
            int u = tid + (i << 8);
            int r = u >> 3, c = u & 7;
            uint32_t so = (uint32_t)(r * 128 + ((c ^ (r & 7)) << 4));
            uint4 zh = make_uint4(0, 0, 0, 0), zl = zh;
            if (q0 + r < NTOK) {
                size_t g = gbase + (size_t)(q0 + r) * DHEAD + c * 8;
                zh = *(const uint4*)(gQh + g);
                zl = *(const uint4*)(gQl + g);
            }
            *(uint4*)(asmem + ASM_QH + so) = zh;
            *(uint4*)(asmem + ASM_QL + so) = zl;
        }

        auto issueKV = [&](int kt) {
            const int k0 = kt * 64;
            const uint32_t base = sb + ASM_KV0 + (uint32_t)(kt & 1) * ASM_KVSZ;
#pragma unroll
            for (int i = 0; i < 2; i++) {
                int u = tid + (i << 8);
                int r = u >> 3, c = u & 7;
                uint32_t so = (uint32_t)(r * 128 + ((c ^ (r & 7)) << 4));
                bool ok = (k0 + r) < NTOK;
                int rr = ok ? (k0 + r) : (NTOK - 1);
                size_t g = gbase + (size_t)rr * DHEAD + c * 8;
                cp_async16(base + so,         gKh + g, ok);
                cp_async16(base + 8192 + so,  gKl + g, ok);
                cp_async16(base + 16384 + so, gVh + g, ok);
                cp_async16(base + 24576 + so, gVl + g, ok);
            }
        };

        float m_[2] = {-1e30f, -1e30f};
        float l_[2] = {0.f, 0.f};
        float o[8][4];
#pragma unroll
        for (int t = 0; t < 8; t++)
#pragma unroll
            for (int j = 0; j < 4; j++) o[t][j] = 0.f;

        issueKV(0); cp_commit();

        for (int kt = 0; kt < 10; kt++) {
            const int k0 = kt * 64;
            cp_wait<0>();
            __syncthreads();

            if (kt + 1 < 10) {
                issueKV(kt + 1);
                cp_commit();
            }

            const uint32_t kvb = sb + ASM_KV0 + (uint32_t)(kt & 1) * ASM_KVSZ;

            // ---- S = Q @ K^T (x3 split) ----
            float s[8][4];
#pragma unroll
            for (int t = 0; t < 8; t++)
#pragma unroll
                for (int j = 0; j < 4; j++) s[t][j] = 0.f;

#pragma unroll
            for (int k16 = 0; k16 < 4; k16++) {
                uint32_t qh[4], ql[4];
                ldsm4(qh, sb + ASM_QH + offQ[k16]);
                ldsm4(ql, sb + ASM_QL + offQ[k16]);
#pragma unroll
                for (int nb = 0; nb < 4; nb++) {
                    int krow = nb * 16 + (lane & 15);
                    uint32_t off = (uint32_t)(krow * 128 +
                                    (((2 * k16 + akc) ^ (krow & 7)) << 4));
                    uint32_t kh[4], kl[4];
                    ldsm4(kh, kvb + off);
                    ldsm4(kl, kvb + 8192 + off);
#pragma unroll
                    for (int nsub = 0; nsub < 2; nsub++) {
                        int t = nb * 2 + nsub;
                        uint32_t bh0 = kh[nsub], bh1 = kh[nsub + 2];
                        uint32_t bl0 = kl[nsub], bl1 = kl[nsub + 2];
                        mma16816(s[t], qh, bh0, bh1);
                        mma16816(s[t], qh, bl0, bl1);
                        mma16816(s[t], ql, bh0, bh1);
                    }
                }
            }

            const bool lastt = (k0 + 64 > NTOK);
            float fi[2];
#pragma unroll
            for (int j = 0; j < 2; j++) {
                float rm = -1e30f;
#pragma unroll
                for (int t = 0; t < 8; t++) {
#pragma unroll
                    for (int c = 0; c < 2; c++) {
                        float v = s[t][j * 2 + c] * scale;
                        if (lastt) {
                            int col = k0 + t * 8 + ((lane & 3) << 1) + c;
                            if (col >= NTOK) v = -1e30f;
                        }
                        s[t][j * 2 + c] = v;
                        rm = fmaxf(rm, v);
                    }
                }
                rm = fmaxf(rm, __shfl_xor_sync(0xffffffffu, rm, 1));
                rm = fmaxf(rm, __shfl_xor_sync(0xffffffffu, rm, 2));
                float mn = fmaxf(m_[j], rm);
                fi[j] = __expf(m_[j] - mn);
                m_[j] = mn;
                float rs = 0.f;
#pragma unroll
                for (int t = 0; t < 8; t++) {
#pragma unroll
                    for (int c = 0; c < 2; c++) {
                        float p = __expf(s[t][j * 2 + c] - mn);
                        s[t][j * 2 + c] = p;
                        rs += p;
                    }
                }
                rs += __shfl_xor_sync(0xffffffffu, rs, 1);
                rs += __shfl_xor_sync(0xffffffffu, rs, 2);
                l_[j] = l_[j] * fi[j] + rs;
            }
#pragma unroll
            for (int t = 0; t < 8; t++) {
                o[t][0] *= fi[0]; o[t][1] *= fi[0];
                o[t][2] *= fi[1]; o[t][3] *= fi[1];
            }

            // ---- O += P @ V (x3 split) ----
#pragma unroll
            for (int t2 = 0; t2 < 4; t2++) {
                uint32_t ph[4], pl[4];
#pragma unroll
                for (int idx = 0; idx < 4; idx++) {
                    int t = 2 * t2 + (idx >> 1);
                    int j = idx & 1;
                    float x0 = s[t][j * 2 + 0];
                    float x1 = s[t][j * 2 + 1];
                    float h0 = __bfloat162float(__float2bfloat16_rn(x0));
                    float h1 = __bfloat162float(__float2bfloat16_rn(x1));
                    ph[idx] = pack_bf16x2(h0, h1);
                    pl[idx] = pack_bf16x2(x0 - h0, x1 - h1);
                }
                const int vm = lane >> 3;
                const int vk = t2 * 16 + ((vm & 1) << 3) + (lane & 7);
#pragma unroll
                for (int nb = 0; nb < 4; nb++) {
                    int vc = nb * 2 + (vm >> 1);
                    uint32_t off = (uint32_t)(vk * 128 + ((vc ^ (vk & 7)) << 4));
                    uint32_t vh[4], vl[4];
                    ldsm4t(vh, kvb + 16384 + off);
                    ldsm4t(vl, kvb + 24576 + off);
                    mma16816(o[nb * 2 + 0], ph, vh[0], vh[1]);
                    mma16816(o[nb * 2 + 0], ph, vl[0], vl[1]);
                    mma16816(o[nb * 2 + 0], pl, vh[0], vh[1]);
                    mma16816(o[nb * 2 + 1], ph, vh[2], vh[3]);
                    mma16816(o[nb * 2 + 1], ph, vl[2], vl[3]);
                    mma16816(o[nb * 2 + 1], pl, vh[2], vh[3]);
                }
            }
        }

        const int b = bh / HEADS;
        const int h = bh % HEADS;
#pragma unroll
        for (int j = 0; j < 2; j++) {
            int n = q0 + m0 + (lane >> 2) + j * 8;
            if (n < NTOK) {
                float inv = 1.f / l_[j];
                size_t gr = (size_t)(b * NTOK + n) * CDIM + h * DHEAD;
#pragma unroll
                for (int t = 0; t < 8; t++) {
                    int col = t * 8 + ((lane & 3) << 1);
                    float x0 = o[t][j * 2 + 0] * inv;
                    float x1 = o[t][j * 2 + 1] * inv;
                    float h0 = __bfloat162float(__float2bfloat16_rn(x0));
                    float h1 = __bfloat162float(__float2bfloat16_rn(x1));
                    *(uint32_t*)(gCh + gr + col) = pack_bf16x2(h0, h1);
                    *(uint32_t*)(gCl + gr + col) = pack_bf16x2(x0 - h0, x1 - h1);
                }
            }
        }
    }
}

// ================================ launch ====================================
extern "C" void kernel_launch(void* const* d_in, const int* in_sizes, int n_in,
                              void* d_out, int out_size) {
    const float* x      = (const float*)d_in[0];
    const float* cosb   = (const float*)d_in[1];
    const float* sinb   = (const float*)d_in[2];
    const float* w_qkv  = (const float*)d_in[3];
    const float* b_qkv  = (const float*)d_in[4];
    const float* w_proj = (const float*)d_in[5];
    const float* b_proj = (const float*)d_in[6];
    float* out = (float*)d_out;

    cudaFuncSetAttribute(k_gemm_mma<true>,
                         cudaFuncAttributeMaxDynamicSharedMemorySize, GT_SMEM);
    cudaFuncSetAttribute(k_gemm_mma<false>,
                         cudaFuncAttributeMaxDynamicSharedMemorySize, GT_SMEM);
    cudaFuncSetAttribute(k_attn_mma,
                         cudaFuncAttributeMaxDynamicSharedMemorySize, ASM_TOTAL);

    int nsm = 148;
    cudaDeviceGetAttribute(&nsm, cudaDevAttrMultiProcessorCount, 0);
    const int maxcta = 2 * nsm;

    __nv_bfloat16 *pAh, *pAl, *pCh, *pCl, *pWqh, *pWql, *pWph, *pWpl;
    cudaGetSymbolAddress((void**)&pAh,  gAh);
    cudaGetSymbolAddress((void**)&pAl,  gAl);
    cudaGetSymbolAddress((void**)&pCh,  gCh);
    cudaGetSymbolAddress((void**)&pCl,  gCl);
    cudaGetSymbolAddress((void**)&pWqh, gWqh);
    cudaGetSymbolAddress((void**)&pWql, gWql);
    cudaGetSymbolAddress((void**)&pWph, gWph);
    cudaGetSymbolAddress((void**)&pWpl, gWpl);

    // 0) fused operand preparation
    k_prep<<<NB_X + NB_WQ + NB_WP, 256>>>(x, w_qkv, w_proj);

    // 1) QKV GEMM + fused RoPE/split (persistent)
    {
        int T = (QKVCOLS / 128) * ((MROWS + 127) / 128);
        int g = T < maxcta ? T : maxcta;
        k_gemm_mma<true><<<g, 256, GT_SMEM>>>(pAh, pAl, pWqh, pWql, b_qkv,
                                              nullptr, MROWS, QKVCOLS,
                                              cosb, sinb);
    }
    // 2) attention (persistent) — writes gCh/gCl
    {
        int g = ATILES < maxcta ? ATILES : maxcta;
        k_attn_mma<<<g, 256, ASM_TOTAL>>>();
    }
    // 3) output projection (persistent)
    {
        int T = (CDIM / 128) * ((MROWS + 127) / 128);
        int g = T < maxcta ? T : maxcta;
        k_gemm_mma<false><<<g, 256, GT_SMEM>>>(pCh, pCl, pWph, pWpl, b_proj,
                                               out, MROWS, CDIM,
                                               nullptr, nullptr);
    }
}

// round 15
// speedup vs baseline: 1.0764x; 1.0764x over previous
#include <cuda_runtime.h>
#include <cuda_bf16.h>
#include <cstdint>
#include <cstddef>

// Problem constants
#define BATCH   16
#define NTOK    577
#define CDIM    768
#define HEADS   12
#define DHEAD   64
#define MROWS   (BATCH * NTOK)          // 9232
#define QKVCOLS (3 * CDIM)              // 2304
#define BHTOT   (BATCH * HEADS)         // 192

// ===================== helpers ==============================================
__device__ __forceinline__ uint32_t smem_to_u32(const void* smem_ptr) {
    uint32_t addr;
    asm("{ .reg .u64 tmp; cvta.to.shared.u64 tmp, %1; cvt.u32.u64 %0, tmp; }"
        : "=r"(addr) : "l"(smem_ptr));
    return addr;
}

__device__ __forceinline__ void ldsm4(uint32_t* r, uint32_t addr) {
    asm volatile("ldmatrix.sync.aligned.m8n8.x4.shared.b16 {%0,%1,%2,%3}, [%4];"
                 : "=r"(r[0]), "=r"(r[1]), "=r"(r[2]), "=r"(r[3]) : "r"(addr));
}

__device__ __forceinline__ void ldsm4t(uint32_t* r, uint32_t addr) {
    asm volatile("ldmatrix.sync.aligned.m8n8.x4.trans.shared.b16 {%0,%1,%2,%3}, [%4];"
                 : "=r"(r[0]), "=r"(r[1]), "=r"(r[2]), "=r"(r[3]) : "r"(addr));
}

__device__ __forceinline__ void mma16816(float* c, const uint32_t* a,
                                         uint32_t b0, uint32_t b1) {
    asm volatile(
        "mma.sync.aligned.m16n8k16.row.col.f32.bf16.bf16.f32 "
        "{%0,%1,%2,%3}, {%4,%5,%6,%7}, {%8,%9}, {%0,%1,%2,%3};"
        : "+f"(c[0]), "+f"(c[1]), "+f"(c[2]), "+f"(c[3])
        : "r"(a[0]), "r"(a[1]), "r"(a[2]), "r"(a[3]), "r"(b0), "r"(b1));
}

// pack(lo, hi) -> bf16x2 register (lo in lower 16 bits)
__device__ __forceinline__ uint32_t pack_bf16x2(float lo, float hi) {
    uint32_t r;
    asm("cvt.rn.bf16x2.f32 %0, %1, %2;" : "=r"(r) : "f"(hi), "f"(lo));
    return r;
}

// 16B async copy; pred=false => zero-fill (reads 0 bytes)
__device__ __forceinline__ void cp_async16(uint32_t dst, const void* src, bool pred) {
    int sz = pred ? 16 : 0;
    asm volatile("cp.async.cg.shared.global [%0], [%1], 16, %2;"
                 :: "r"(dst), "l"(src), "r"(sz) : "memory");
}
__device__ __forceinline__ void cp_commit() {
    asm volatile("cp.async.commit_group;" ::: "memory");
}
template <int N>
__device__ __forceinline__ void cp_wait() {
    asm volatile("cp.async.wait_group %0;" :: "n"(N) : "memory");
}

// ---------------- scratch (no allocations allowed -> device globals) --------
// bf16 hi/lo split operands for tensor-core GEMMs
__device__ __nv_bfloat16 gAh[(size_t)MROWS * CDIM];           // x split
__device__ __nv_bfloat16 gAl[(size_t)MROWS * CDIM];
__device__ __nv_bfloat16 gCh[(size_t)MROWS * CDIM];           // attn-out split
__device__ __nv_bfloat16 gCl[(size_t)MROWS * CDIM];
__device__ __nv_bfloat16 gWqh[(size_t)QKVCOLS * CDIM];        // w_qkv^T split
__device__ __nv_bfloat16 gWql[(size_t)QKVCOLS * CDIM];
__device__ __nv_bfloat16 gWph[(size_t)CDIM * CDIM];           // w_proj^T split
__device__ __nv_bfloat16 gWpl[(size_t)CDIM * CDIM];

// bf16 hi/lo Q/K/V, (B*H, N, D)
__device__ __nv_bfloat16 gQh[(size_t)BHTOT * NTOK * DHEAD];
__device__ __nv_bfloat16 gQl[(size_t)BHTOT * NTOK * DHEAD];
__device__ __nv_bfloat16 gKh[(size_t)BHTOT * NTOK * DHEAD];
__device__ __nv_bfloat16 gKl[(size_t)BHTOT * NTOK * DHEAD];
__device__ __nv_bfloat16 gVh[(size_t)BHTOT * NTOK * DHEAD];
__device__ __nv_bfloat16 gVl[(size_t)BHTOT * NTOK * DHEAD];

// =============== fused operand prep (split x + transpose/split weights) =====
#define NB_X  ((MROWS * CDIM / 4 + 255) / 256)           // 6924
#define NB_WQ ((QKVCOLS / 32) * (CDIM / 32))             // 1728
#define NB_WP ((CDIM / 32) * (CDIM / 32))                // 576

__device__ __forceinline__ void wsplit_body(const float* __restrict__ w,
                                            __nv_bfloat16* __restrict__ oh,
                                            __nv_bfloat16* __restrict__ ol,
                                            int K, int N, int bx, int by,
                                            int tid, float (*t)[33]) {
    int n0 = bx * 32, k0 = by * 32;
    int tx = tid & 31, ty = tid >> 5;
#pragma unroll
    for (int j = 0; j < 32; j += 8)
        t[ty + j][tx] = w[(size_t)(k0 + ty + j) * N + n0 + tx];
    __syncthreads();
#pragma unroll
    for (int j = 0; j < 32; j += 8) {
        float v = t[tx][ty + j];
        int n = n0 + ty + j, k = k0 + tx;
        __nv_bfloat16 h = __float2bfloat16_rn(v);
        __nv_bfloat16 l = __float2bfloat16_rn(v - __bfloat162float(h));
        oh[(size_t)n * K + k] = h;
        ol[(size_t)n * K + k] = l;
    }
}

__global__ __launch_bounds__(256) void k_prep(const float* __restrict__ x,
                                              const float* __restrict__ w_qkv,
                                              const float* __restrict__ w_proj) {
    __shared__ float t[32][33];
    const int b = blockIdx.x;
    const int tid = threadIdx.x;
    if (b < NB_X) {
        int i = b * 256 + tid;
        const int n4 = MROWS * CDIM / 4;
        if (i < n4) {
            float4 v = ((const float4*)x)[i];
            float f[4] = {v.x, v.y, v.z, v.w};
            __align__(8) __nv_bfloat16 h[4];
            __align__(8) __nv_bfloat16 l[4];
#pragma unroll
            for (int j = 0; j < 4; j++) {
                h[j] = __float2bfloat16_rn(f[j]);
                l[j] = __float2bfloat16_rn(f[j] - __bfloat162float(h[j]));
            }
            *(uint2*)(gAh + 4 * (size_t)i) = *(uint2*)h;
            *(uint2*)(gAl + 4 * (size_t)i) = *(uint2*)l;
        }
    } else if (b < NB_X + NB_WQ) {
        int bb = b - NB_X;
        wsplit_body(w_qkv, gWqh, gWql, CDIM, QKVCOLS,
                    bb % (QKVCOLS / 32), bb / (QKVCOLS / 32), tid, t);
    } else {
        int bb = b - NB_X - NB_WQ;
        wsplit_body(w_proj, gWph, gWpl, CDIM, CDIM,
                    bb % (CDIM / 32), bb / (CDIM / 32), tid, t);
    }
}

// =================== HMMA bf16x3 GEMM: C = A@B + bias =======================
// 3-stage cp.async pipeline; 2 CTAs/SM. Tile 128x128, BK=32, 8 warps (2x4).
// ROPE=true: qkv GEMM — epilogue applies RoPE + bf16 hi/lo split and scatters
// straight into gQ/gK/gV.
#define GT_TILE 8192                    // 128 x 32 bf16
#define GT_BUF  (4 * GT_TILE)           // 32KB / stage (Ah,Al,Bh,Bl)
#define GT_SMEM (3 * GT_BUF)            // 96KB, 3 stages

template <bool ROPE>
__global__ __launch_bounds__(256, 2) void k_gemm_mma(
    const __nv_bfloat16* __restrict__ Ah, const __nv_bfloat16* __restrict__ Al,
    const __nv_bfloat16* __restrict__ Bh, const __nv_bfloat16* __restrict__ Bl,
    const float* __restrict__ bias, float* __restrict__ C, int M, int N,
    const float* __restrict__ cosb, const float* __restrict__ sinb) {
    extern __shared__ __align__(128) char smem[];
    const uint32_t sbase = smem_to_u32(smem);

    const int tid  = threadIdx.x;
    const int lane = tid & 31;
    const int wid  = tid >> 5;
    const int wm   = wid >> 2;
    const int wn   = wid & 3;
    const int block_row = blockIdx.y * 128;
    const int block_col = blockIdx.x * 128;

    // global->smem chunk mapping (2 chunks per thread per tile)
    const int u0 = tid, u1 = tid + 256;
    const int r0 = u0 >> 2, c0 = u0 & 3;
    const int r1 = u1 >> 2, c1 = u1 & 3;
    const uint32_t so0 = (uint32_t)(r0 * 64 + ((c0 ^ ((r0 >> 1) & 3)) << 4));
    const uint32_t so1 = (uint32_t)(r1 * 64 + ((c1 ^ ((r1 >> 1) & 3)) << 4));
    const bool a0ok = (block_row + r0) < M;
    const bool a1ok = (block_row + r1) < M;
    const int ar0 = a0ok ? (block_row + r0) : (M - 1);
    const int ar1 = a1ok ? (block_row + r1) : (M - 1);
    const size_t gA0 = (size_t)ar0 * CDIM + c0 * 8;
    const size_t gA1 = (size_t)ar1 * CDIM + c1 * 8;
    const size_t gB0 = (size_t)(block_col + r0) * CDIM + c0 * 8;
    const size_t gB1 = (size_t)(block_col + r1) * CDIM + c1 * 8;

    // ldmatrix source offsets (loop invariant)
    const int lrow = lane & 15;
    const int lkc  = lane >> 4;
    uint32_t offA[2][4], offB[2][2];
#pragma unroll
    for (int kk2 = 0; kk2 < 2; kk2++) {
        int cc = kk2 * 2 + lkc;
#pragma unroll
        for (int mi = 0; mi < 4; mi++) {
            int rr = wm * 64 + mi * 16 + lrow;
            offA[kk2][mi] = (uint32_t)(rr * 64 + ((cc ^ ((rr >> 1) & 3)) << 4));
        }
#pragma unroll
        for (int nb = 0; nb < 2; nb++) {
            int rr = wn * 32 + nb * 16 + lrow;
            offB[kk2][nb] = (uint32_t)(rr * 64 + ((cc ^ ((rr >> 1) & 3)) << 4));
        }
    }

    float acc[4][4][4];
#pragma unroll
    for (int mi = 0; mi < 4; mi++)
#pragma unroll
        for (int ni = 0; ni < 4; ni++)
#pragma unroll
            for (int j = 0; j < 4; j++) acc[mi][ni][j] = 0.f;

    const int NSTAGE = CDIM / 32;        // 24

    auto issue = [&](int s, int buf) {
        const int ko = s * 32;
        const uint32_t b = sbase + (uint32_t)buf * GT_BUF;
        cp_async16(b + so0,               Ah + gA0 + ko, a0ok);
        cp_async16(b + so1,               Ah + gA1 + ko, a1ok);
        cp_async16(b + GT_TILE + so0,     Al + gA0 + ko, a0ok);
        cp_async16(b + GT_TILE + so1,     Al + gA1 + ko, a1ok);
        cp_async16(b + 2 * GT_TILE + so0, Bh + gB0 + ko, true);
        cp_async16(b + 2 * GT_TILE + so1, Bh + gB1 + ko, true);
        cp_async16(b + 3 * GT_TILE + so0, Bl + gB0 + ko, true);
        cp_async16(b + 3 * GT_TILE + so1, Bl + gB1 + ko, true);
    };

    issue(0, 0); cp_commit();
    issue(1, 1); cp_commit();

    int buf = 0;
    for (int s = 0; s < NSTAGE; s++) {
        if (s == NSTAGE - 1) cp_wait<0>();   // drain: guarantee last stage landed
        else                 cp_wait<1>();
        __syncthreads();

        if (s + 2 < NSTAGE) {
            issue(s + 2, (s + 2) % 3);
            cp_commit();
        }

        const uint32_t tbase = sbase + (uint32_t)buf * GT_BUF;
#pragma unroll
        for (int kk2 = 0; kk2 < 2; kk2++) {
            uint32_t ah[4][4], al[4][4];
#pragma unroll
            for (int mi = 0; mi < 4; mi++) {
                ldsm4(ah[mi], tbase + offA[kk2][mi]);
                ldsm4(al[mi], tbase + GT_TILE + offA[kk2][mi]);
            }
#pragma unroll
            for (int nb = 0; nb < 2; nb++) {
                uint32_t bh[4], bl[4];
                ldsm4(bh, tbase + 2 * GT_TILE + offB[kk2][nb]);
                ldsm4(bl, tbase + 3 * GT_TILE + offB[kk2][nb]);
#pragma unroll
                for (int mi = 0; mi < 4; mi++) {
#pragma unroll
                    for (int nsub = 0; nsub < 2; nsub++) {
                        const int ni = nb * 2 + nsub;
                        uint32_t b0 = bh[nsub], b1 = bh[nsub + 2];
                        uint32_t c0r = bl[nsub], c1r = bl[nsub + 2];
                        mma16816(acc[mi][ni], ah[mi], b0, b1);
                        mma16816(acc[mi][ni], ah[mi], c0r, c1r);
                        mma16816(acc[mi][ni], al[mi], b0, b1);
                    }
                }
            }
        }
        buf = (buf + 1) % 3;
    }

    // ---- epilogue ----
    const int erow = lane >> 2;
    const int ecol = (lane & 3) << 1;

    if (!ROPE) {
#pragma unroll
        for (int mi = 0; mi < 4; mi++) {
#pragma unroll
            for (int ni = 0; ni < 4; ni++) {
                int r = block_row + wm * 64 + mi * 16 + erow;
                int col = block_col + wn * 32 + ni * 8 + ecol;
                float2 bv = *(const float2*)(bias + col);
                if (r < M) {
                    float2 o = make_float2(acc[mi][ni][0] + bv.x,
                                           acc[mi][ni][1] + bv.y);
                    *(float2*)(C + (size_t)r * N + col) = o;
                }
                if (r + 8 < M) {
                    float2 o = make_float2(acc[mi][ni][2] + bv.x,
                                           acc[mi][ni][3] + bv.y);
                    *(float2*)(C + (size_t)(r + 8) * N + col) = o;
                }
            }
        }
    } else {
        // fused RoPE + bf16 hi/lo split + scatter to Q/K/V
        const int sec = block_col / CDIM;               // 0=Q,1=K,2=V (const/CTA)
        const int hbase = (block_col % CDIM) / DHEAD;
        __nv_bfloat16* dh = sec == 0 ? gQh : (sec == 1 ? gKh : gVh);
        __nv_bfloat16* dl = sec == 0 ? gQl : (sec == 1 ? gKl : gVl);
#pragma unroll
        for (int mi = 0; mi < 4; mi++) {
#pragma unroll
            for (int rp = 0; rp < 2; rp++) {
                int r = block_row + wm * 64 + mi * 16 + erow + rp * 8;
                if (r >= M) continue;
                int bidx = r / NTOK;
                int n = r - bidx * NTOK;
#pragma unroll
                for (int ni = 0; ni < 4; ni++) {
                    int lc = wn * 32 + ni * 8 + ecol;
                    int col = block_col + lc;
                    float v0 = acc[mi][ni][rp * 2 + 0] + bias[col];
                    float v1 = acc[mi][ni][rp * 2 + 1] + bias[col + 1];
                    int d = lc & 63;
                    int h = hbase + (lc >> 6);
                    if (sec < 2 && n > 0) {
                        float cc = cosb[(size_t)(n - 1) * 32 + (d >> 1)];
                        float ss = sinb[(size_t)(n - 1) * 32 + (d >> 1)];
                        float t0 = v0 * cc - v1 * ss;
                        float t1 = v0 * ss + v1 * cc;
                        v0 = t0; v1 = t1;
                    }
                    float h0 = __bfloat162float(__float2bfloat16_rn(v0));
                    float h1 = __bfloat162float(__float2bfloat16_rn(v1));
                    size_t o = ((size_t)(bidx * HEADS + h) * NTOK + n) * DHEAD + d;
                    *(uint32_t*)(dh + o) = pack_bf16x2(h0, h1);
                    *(uint32_t*)(dl + o) = pack_bf16x2(v0 - h0, v1 - h1);
                }
            }
        }
    }
}

// ============== Flash attention on HMMA, bf16x3, 128 q-rows/CTA =============
// 2-stage cp.async double buffer for K/V. smem 96KB; 2 CTAs/SM.
#define ASM_QH   0
#define ASM_QL   16384
#define ASM_KV0  32768
#define ASM_KVSZ 32768                 // KH+0, KL+8192, VH+16384, VL+24576
#define ASM_TOTAL 98304

__global__ __launch_bounds__(256, 2) void k_attn_mma() {
    extern __shared__ __align__(128) char asmem[];
    const uint32_t sb = smem_to_u32(asmem);
    const int tid = threadIdx.x;
    const int lane = tid & 31;
    const int wid = tid >> 5;
    const int bh = blockIdx.y;
    const int q0 = blockIdx.x * 128;
    const size_t gbase = (size_t)bh * NTOK * DHEAD;

    // ---- load Q tile (persistent) ----
#pragma unroll
    for (int i = 0; i < 4; i++) {
        int u = tid + (i << 8);
        int r = u >> 3, c = u & 7;
        uint32_t so = (uint32_t)(r * 128 + ((c ^ (r & 7)) << 4));
        uint4 zh = make_uint4(0, 0, 0, 0), zl = zh;
        if (q0 + r < NTOK) {
            size_t g = gbase + (size_t)(q0 + r) * DHEAD + c * 8;
            zh = *(const uint4*)(gQh + g);
            zl = *(const uint4*)(gQl + g);
        }
        *(uint4*)(asmem + ASM_QH + so) = zh;
        *(uint4*)(asmem + ASM_QL + so) = zl;
    }

    // ---- K/V async stage loader ----
    auto issueKV = [&](int kt) {
        const int k0 = kt * 64;
        const uint32_t base = sb + ASM_KV0 + (uint32_t)(kt & 1) * ASM_KVSZ;
#pragma unroll
        for (int i = 0; i < 2; i++) {
            int u = tid + (i << 8);
            int r = u >> 3, c = u & 7;
            uint32_t so = (uint32_t)(r * 128 + ((c ^ (r & 7)) << 4));
            bool ok = (k0 + r) < NTOK;
            int rr = ok ? (k0 + r) : (NTOK - 1);
            size_t g = gbase + (size_t)rr * DHEAD + c * 8;
            cp_async16(base + so,         gKh + g, ok);
            cp_async16(base + 8192 + so,  gKl + g, ok);
            cp_async16(base + 16384 + so, gVh + g, ok);
            cp_async16(base + 24576 + so, gVl + g, ok);
        }
    };

    const int m0 = wid * 16;
    const int alr = m0 + (lane & 15);
    const int akc = lane >> 4;
    uint32_t offQ[4];
#pragma unroll
    for (int k16 = 0; k16 < 4; k16++)
        offQ[k16] = (uint32_t)(alr * 128 + (((2 * k16 + akc) ^ (alr & 7)) << 4));

    float m_[2] = {-1e30f, -1e30f};
    float l_[2] = {0.f, 0.f};
    float o[8][4];
#pragma unroll
    for (int t = 0; t < 8; t++)
#pragma unroll
        for (int j = 0; j < 4; j++) o[t][j] = 0.f;

    const float scale = 0.125f;

    issueKV(0); cp_commit();

    for (int kt = 0; kt < 10; kt++) {
        const int k0 = kt * 64;
        cp_wait<0>();          // stage kt landed
        __syncthreads();       // visible + all warps done with stage kt-1 buffer

        if (kt + 1 < 10) {     // prefetch overlaps compute of stage kt
            issueKV(kt + 1);
            cp_commit();
        }

        const uint32_t kvb = sb + ASM_KV0 + (uint32_t)(kt & 1) * ASM_KVSZ;

        // ---- S = Q @ K^T (x3 split) ----
        float s[8][4];
#pragma unroll
        for (int t = 0; t < 8; t++)
#pragma unroll
            for (int j = 0; j < 4; j++) s[t][j] = 0.f;

#pragma unroll
        for (int k16 = 0; k16 < 4; k16++) {
            uint32_t qh[4], ql[4];
            ldsm4(qh, sb + ASM_QH + offQ[k16]);
            ldsm4(ql, sb + ASM_QL + offQ[k16]);
#pragma unroll
            for (int nb = 0; nb < 4; nb++) {
                int krow = nb * 16 + (lane & 15);
                uint32_t off = (uint32_t)(krow * 128 +
                                (((2 * k16 + akc) ^ (krow & 7)) << 4));
                uint32_t kh[4], kl[4];
                ldsm4(kh, kvb + off);
                ldsm4(kl, kvb + 8192 + off);
#pragma unroll
                for (int nsub = 0; nsub < 2; nsub++) {
                    int t = nb * 2 + nsub;
                    uint32_t bh0 = kh[nsub], bh1 = kh[nsub + 2];
                    uint32_t bl0 = kl[nsub], bl1 = kl[nsub + 2];
                    mma16816(s[t], qh, bh0, bh1);
                    mma16816(s[t], qh, bl0, bl1);
                    mma16816(s[t], ql, bh0, bh1);
                }
            }
        }

        const bool lastt = (k0 + 64 > NTOK);
        float fi[2];
#pragma unroll
        for (int j = 0; j < 2; j++) {
            float rm = -1e30f;
#pragma unroll
            for (int t = 0; t < 8; t++) {
#pragma unroll
                for (int c = 0; c < 2; c++) {
                    float v = s[t][j * 2 + c] * scale;
                    if (lastt) {
                        int col = k0 + t * 8 + ((lane & 3) << 1) + c;
                        if (col >= NTOK) v = -1e30f;
                    }
                    s[t][j * 2 + c] = v;
                    rm = fmaxf(rm, v);
                }
            }
            rm = fmaxf(rm, __shfl_xor_sync(0xffffffffu, rm, 1));
            rm = fmaxf(rm, __shfl_xor_sync(0xffffffffu, rm, 2));
            float mn = fmaxf(m_[j], rm);
            fi[j] = __expf(m_[j] - mn);
            m_[j] = mn;
            float rs = 0.f;
#pragma unroll
            for (int t = 0; t < 8; t++) {
#pragma unroll
                for (int c = 0; c < 2; c++) {
                    float p = __expf(s[t][j * 2 + c] - mn);
                    s[t][j * 2 + c] = p;
                    rs += p;
                }
            }
            rs += __shfl_xor_sync(0xffffffffu, rs, 1);
            rs += __shfl_xor_sync(0xffffffffu, rs, 2);
            l_[j] = l_[j] * fi[j] + rs;
        }
#pragma unroll
        for (int t = 0; t < 8; t++) {
            o[t][0] *= fi[0]; o[t][1] *= fi[0];
            o[t][2] *= fi[1]; o[t][3] *= fi[1];
        }

        // ---- O += P @ V (x3 split) ----
#pragma unroll
        for (int t2 = 0; t2 < 4; t2++) {
            uint32_t ph[4], pl[4];
#pragma unroll
            for (int idx = 0; idx < 4; idx++) {
                int t = 2 * t2 + (idx >> 1);
                int j = idx & 1;
                float x0 = s[t][j * 2 + 0];
                float x1 = s[t][j * 2 + 1];
                float h0 = __bfloat162float(__float2bfloat16_rn(x0));
                float h1 = __bfloat162float(__float2bfloat16_rn(x1));
                ph[idx] = pack_bf16x2(h0, h1);
                pl[idx] = pack_bf16x2(x0 - h0, x1 - h1);
            }
            const int vm = lane >> 3;
            const int vk = t2 * 16 + ((vm & 1) << 3) + (lane & 7);
#pragma unroll
            for (int nb = 0; nb < 4; nb++) {
                int vc = nb * 2 + (vm >> 1);
                uint32_t off = (uint32_t)(vk * 128 + ((vc ^ (vk & 7)) << 4));
                uint32_t vh[4], vl[4];
                ldsm4t(vh, kvb + 16384 + off);
                ldsm4t(vl, kvb + 24576 + off);
                mma16816(o[nb * 2 + 0], ph, vh[0], vh[1]);
                mma16816(o[nb * 2 + 0], ph, vl[0], vl[1]);
                mma16816(o[nb * 2 + 0], pl, vh[0], vh[1]);
                mma16816(o[nb * 2 + 1], ph, vh[2], vh[3]);
                mma16816(o[nb * 2 + 1], ph, vl[2], vl[3]);
                mma16816(o[nb * 2 + 1], pl, vh[2], vh[3]);
            }
        }
    }

    const int b = bh / HEADS;
    const int h = bh % HEADS;
#pragma unroll
    for (int j = 0; j < 2; j++) {
        int n = q0 + m0 + (lane >> 2) + j * 8;
        if (n < NTOK) {
            float inv = 1.f / l_[j];
            size_t gr = (size_t)(b * NTOK + n) * CDIM + h * DHEAD;
#pragma unroll
            for (int t = 0; t < 8; t++) {
                int col = t * 8 + ((lane & 3) << 1);
                float x0 = o[t][j * 2 + 0] * inv;
                float x1 = o[t][j * 2 + 1] * inv;
                float h0 = __bfloat162float(__float2bfloat16_rn(x0));
                float h1 = __bfloat162float(__float2bfloat16_rn(x1));
                *(uint32_t*)(gCh + gr + col) = pack_bf16x2(h0, h1);
                *(uint32_t*)(gCl + gr + col) = pack_bf16x2(x0 - h0, x1 - h1);
            }
        }
    }
}

// ================================ launch ====================================
extern "C" void kernel_launch(void* const* d_in, const int* in_sizes, int n_in,
                              void* d_out, int out_size) {
    const float* x      = (const float*)d_in[0];
    const float* cosb   = (const float*)d_in[1];
    const float* sinb   = (const float*)d_in[2];
    const float* w_qkv  = (const float*)d_in[3];
    const float* b_qkv  = (const float*)d_in[4];
    const float* w_proj = (const float*)d_in[5];
    const float* b_proj = (const float*)d_in[6];
    float* out = (float*)d_out;

    cudaFuncSetAttribute(k_gemm_mma<true>,
                         cudaFuncAttributeMaxDynamicSharedMemorySize, GT_SMEM);
    cudaFuncSetAttribute(k_gemm_mma<false>,
                         cudaFuncAttributeMaxDynamicSharedMemorySize, GT_SMEM);
    cudaFuncSetAttribute(k_attn_mma,
                         cudaFuncAttributeMaxDynamicSharedMemorySize, ASM_TOTAL);

    __nv_bfloat16 *pAh, *pAl, *pCh, *pCl, *pWqh, *pWql, *pWph, *pWpl;
    cudaGetSymbolAddress((void**)&pAh,  gAh);
    cudaGetSymbolAddress((void**)&pAl,  gAl);
    cudaGetSymbolAddress((void**)&pCh,  gCh);
    cudaGetSymbolAddress((void**)&pCl,  gCl);
    cudaGetSymbolAddress((void**)&pWqh, gWqh);
    cudaGetSymbolAddress((void**)&pWql, gWql);
    cudaGetSymbolAddress((void**)&pWph, gWph);
    cudaGetSymbolAddress((void**)&pWpl, gWpl);

    // 0) fused operand preparation
    k_prep<<<NB_X + NB_WQ + NB_WP, 256>>>(x, w_qkv, w_proj);

    // 1) QKV GEMM + fused RoPE/split (HMMA bf16x3, cp.async pipeline)
    {
        dim3 grid(QKVCOLS / 128, (MROWS + 127) / 128);
        k_gemm_mma<true><<<grid, 256, GT_SMEM>>>(pAh, pAl, pWqh, pWql, b_qkv,
                                                 nullptr, MROWS, QKVCOLS,
                                                 cosb, sinb);
    }
    // 2) attention (HMMA bf16x3, double-buffered K/V) — writes gCh/gCl
    {
        dim3 grid((NTOK + 127) / 128, BHTOT);
        k_attn_mma<<<grid, 256, ASM_TOTAL>>>();
    }
    // 3) output projection (HMMA bf16x3, cp.async pipeline)
    {
        dim3 grid(CDIM / 128, (MROWS + 127) / 128);
        k_gemm_mma<false><<<grid, 256, GT_SMEM>>>(pCh, pCl, pWph, pWpl, b_proj,
                                                  out, MROWS, CDIM,
                                                  nullptr, nullptr);
    }
}

// round 16
// speedup vs baseline: 1.0904x; 1.0130x over previous
#include <cuda_runtime.h>
#include <cuda_bf16.h>
#include <cstdint>
#include <cstddef>

// Problem constants
#define BATCH   16
#define NTOK    577
#define CDIM    768
#define HEADS   12
#define DHEAD   64
#define MROWS   (BATCH * NTOK)          // 9232
#define QKVCOLS (3 * CDIM)              // 2304
#define BHTOT   (BATCH * HEADS)         // 192

// ===================== helpers ==============================================
__device__ __forceinline__ uint32_t smem_to_u32(const void* smem_ptr) {
    uint32_t addr;
    asm("{ .reg .u64 tmp; cvta.to.shared.u64 tmp, %1; cvt.u32.u64 %0, tmp; }"
        : "=r"(addr) : "l"(smem_ptr));
    return addr;
}

__device__ __forceinline__ void ldsm4(uint32_t* r, uint32_t addr) {
    asm volatile("ldmatrix.sync.aligned.m8n8.x4.shared.b16 {%0,%1,%2,%3}, [%4];"
                 : "=r"(r[0]), "=r"(r[1]), "=r"(r[2]), "=r"(r[3]) : "r"(addr));
}

__device__ __forceinline__ void ldsm4t(uint32_t* r, uint32_t addr) {
    asm volatile("ldmatrix.sync.aligned.m8n8.x4.trans.shared.b16 {%0,%1,%2,%3}, [%4];"
                 : "=r"(r[0]), "=r"(r[1]), "=r"(r[2]), "=r"(r[3]) : "r"(addr));
}

__device__ __forceinline__ void mma16816(float* c, const uint32_t* a,
                                         uint32_t b0, uint32_t b1) {
    asm volatile(
        "mma.sync.aligned.m16n8k16.row.col.f32.bf16.bf16.f32 "
        "{%0,%1,%2,%3}, {%4,%5,%6,%7}, {%8,%9}, {%0,%1,%2,%3};"
        : "+f"(c[0]), "+f"(c[1]), "+f"(c[2]), "+f"(c[3])
        : "r"(a[0]), "r"(a[1]), "r"(a[2]), "r"(a[3]), "r"(b0), "r"(b1));
}

// pack(lo, hi) -> bf16x2 register (lo in lower 16 bits)
__device__ __forceinline__ uint32_t pack_bf16x2(float lo, float hi) {
    uint32_t r;
    asm("cvt.rn.bf16x2.f32 %0, %1, %2;" : "=r"(r) : "f"(hi), "f"(lo));
    return r;
}

// 16B async copy; pred=false => zero-fill (reads 0 bytes)
__device__ __forceinline__ void cp_async16(uint32_t dst, const void* src, bool pred) {
    int sz = pred ? 16 : 0;
    asm volatile("cp.async.cg.shared.global [%0], [%1], 16, %2;"
                 :: "r"(dst), "l"(src), "r"(sz) : "memory");
}
__device__ __forceinline__ void cp_commit() {
    asm volatile("cp.async.commit_group;" ::: "memory");
}
template <int N>
__device__ __forceinline__ void cp_wait() {
    asm volatile("cp.async.wait_group %0;" :: "n"(N) : "memory");
}

// ---------------- scratch (no allocations allowed -> device globals) --------
// bf16 hi/lo split operands for tensor-core GEMMs
__device__ __nv_bfloat16 gAh[(size_t)MROWS * CDIM];           // x split
__device__ __nv_bfloat16 gAl[(size_t)MROWS * CDIM];
__device__ __nv_bfloat16 gCh[(size_t)MROWS * CDIM];           // attn-out split
__device__ __nv_bfloat16 gCl[(size_t)MROWS * CDIM];
__device__ __nv_bfloat16 gWqh[(size_t)QKVCOLS * CDIM];        // w_qkv^T split
__device__ __nv_bfloat16 gWql[(size_t)QKVCOLS * CDIM];
__device__ __nv_bfloat16 gWph[(size_t)CDIM * CDIM];           // w_proj^T split
__device__ __nv_bfloat16 gWpl[(size_t)CDIM * CDIM];

// bf16 hi/lo Q/K/V, (B*H, N, D)
__device__ __nv_bfloat16 gQh[(size_t)BHTOT * NTOK * DHEAD];
__device__ __nv_bfloat16 gQl[(size_t)BHTOT * NTOK * DHEAD];
__device__ __nv_bfloat16 gKh[(size_t)BHTOT * NTOK * DHEAD];
__device__ __nv_bfloat16 gKl[(size_t)BHTOT * NTOK * DHEAD];
__device__ __nv_bfloat16 gVh[(size_t)BHTOT * NTOK * DHEAD];
__device__ __nv_bfloat16 gVl[(size_t)BHTOT * NTOK * DHEAD];

// =============== fused operand prep (split x + transpose/split weights) =====
#define NB_X  ((MROWS * CDIM / 4 + 1023) / 1024)         // 4 float4 per thread
#define NB_WQ ((QKVCOLS / 32) * (CDIM / 32))             // 1728
#define NB_WP ((CDIM / 32) * (CDIM / 32))                // 576

__device__ __forceinline__ void wsplit_body(const float* __restrict__ w,
                                            __nv_bfloat16* __restrict__ oh,
                                            __nv_bfloat16* __restrict__ ol,
                                            int K, int N, int bx, int by,
                                            int tid, float (*t)[33]) {
    int n0 = bx * 32, k0 = by * 32;
    int tx = tid & 31, ty = tid >> 5;
#pragma unroll
    for (int j = 0; j < 32; j += 8)
        t[ty + j][tx] = w[(size_t)(k0 + ty + j) * N + n0 + tx];
    __syncthreads();
#pragma unroll
    for (int j = 0; j < 32; j += 8) {
        float v = t[tx][ty + j];
        int n = n0 + ty + j, k = k0 + tx;
        __nv_bfloat16 h = __float2bfloat16_rn(v);
        __nv_bfloat16 l = __float2bfloat16_rn(v - __bfloat162float(h));
        oh[(size_t)n * K + k] = h;
        ol[(size_t)n * K + k] = l;
    }
}

__global__ __launch_bounds__(256) void k_prep(const float* __restrict__ x,
                                              const float* __restrict__ w_qkv,
                                              const float* __restrict__ w_proj) {
    __shared__ float t[32][33];
    const int b = blockIdx.x;
    const int tid = threadIdx.x;
    if (b < NB_X) {
        const int n4 = MROWS * CDIM / 4;
#pragma unroll
        for (int j = 0; j < 4; j++) {
            int i = b * 1024 + j * 256 + tid;
            if (i < n4) {
                float4 v = ((const float4*)x)[i];
                float f[4] = {v.x, v.y, v.z, v.w};
                __align__(8) __nv_bfloat16 h[4];
                __align__(8) __nv_bfloat16 l[4];
#pragma unroll
                for (int q = 0; q < 4; q++) {
                    h[q] = __float2bfloat16_rn(f[q]);
                    l[q] = __float2bfloat16_rn(f[q] - __bfloat162float(h[q]));
                }
                *(uint2*)(gAh + 4 * (size_t)i) = *(uint2*)h;
                *(uint2*)(gAl + 4 * (size_t)i) = *(uint2*)l;
            }
        }
    } else if (b < NB_X + NB_WQ) {
        int bb = b - NB_X;
        wsplit_body(w_qkv, gWqh, gWql, CDIM, QKVCOLS,
                    bb % (QKVCOLS / 32), bb / (QKVCOLS / 32), tid, t);
    } else {
        int bb = b - NB_X - NB_WQ;
        wsplit_body(w_proj, gWph, gWpl, CDIM, CDIM,
                    bb % (CDIM / 32), bb / (CDIM / 32), tid, t);
    }
}

// =================== HMMA bf16x3 GEMM: C = A@B + bias =======================
// 3-stage cp.async pipeline; 2 CTAs/SM. Tile 128x128, BK=32, 8 warps (2x4).
// Split-pass ordering: each of the 3 bf16x3 products sweeps all 8 accumulators
// before revisiting one (dependency distance 8 -> HMMA latency hidden).
#define GT_TILE 8192                    // 128 x 32 bf16
#define GT_BUF  (4 * GT_TILE)           // 32KB / stage (Ah,Al,Bh,Bl)
#define GT_SMEM (3 * GT_BUF)            // 96KB, 3 stages

template <bool ROPE>
__global__ __launch_bounds__(256, 2) void k_gemm_mma(
    const __nv_bfloat16* __restrict__ Ah, const __nv_bfloat16* __restrict__ Al,
    const __nv_bfloat16* __restrict__ Bh, const __nv_bfloat16* __restrict__ Bl,
    const float* __restrict__ bias, float* __restrict__ C, int M, int N,
    const float* __restrict__ cosb, const float* __restrict__ sinb) {
    extern __shared__ __align__(128) char smem[];
    const uint32_t sbase = smem_to_u32(smem);

    const int tid  = threadIdx.x;
    const int lane = tid & 31;
    const int wid  = tid >> 5;
    const int wm   = wid >> 2;
    const int wn   = wid & 3;
    const int block_row = blockIdx.y * 128;
    const int block_col = blockIdx.x * 128;

    // global->smem chunk mapping (2 chunks per thread per tile)
    const int u0 = tid, u1 = tid + 256;
    const int r0 = u0 >> 2, c0 = u0 & 3;
    const int r1 = u1 >> 2, c1 = u1 & 3;
    const uint32_t so0 = (uint32_t)(r0 * 64 + ((c0 ^ ((r0 >> 1) & 3)) << 4));
    const uint32_t so1 = (uint32_t)(r1 * 64 + ((c1 ^ ((r1 >> 1) & 3)) << 4));
    const bool a0ok = (block_row + r0) < M;
    const bool a1ok = (block_row + r1) < M;
    const int ar0 = a0ok ? (block_row + r0) : (M - 1);
    const int ar1 = a1ok ? (block_row + r1) : (M - 1);
    const size_t gA0 = (size_t)ar0 * CDIM + c0 * 8;
    const size_t gA1 = (size_t)ar1 * CDIM + c1 * 8;
    const size_t gB0 = (size_t)(block_col + r0) * CDIM + c0 * 8;
    const size_t gB1 = (size_t)(block_col + r1) * CDIM + c1 * 8;

    // ldmatrix source offsets (loop invariant)
    const int lrow = lane & 15;
    const int lkc  = lane >> 4;
    uint32_t offA[2][4], offB[2][2];
#pragma unroll
    for (int kk2 = 0; kk2 < 2; kk2++) {
        int cc = kk2 * 2 + lkc;
#pragma unroll
        for (int mi = 0; mi < 4; mi++) {
            int rr = wm * 64 + mi * 16 + lrow;
            offA[kk2][mi] = (uint32_t)(rr * 64 + ((cc ^ ((rr >> 1) & 3)) << 4));
        }
#pragma unroll
        for (int nb = 0; nb < 2; nb++) {
            int rr = wn * 32 + nb * 16 + lrow;
            offB[kk2][nb] = (uint32_t)(rr * 64 + ((cc ^ ((rr >> 1) & 3)) << 4));
        }
    }

    float acc[4][4][4];
#pragma unroll
    for (int mi = 0; mi < 4; mi++)
#pragma unroll
        for (int ni = 0; ni < 4; ni++)
#pragma unroll
            for (int j = 0; j < 4; j++) acc[mi][ni][j] = 0.f;

    const int NSTAGE = CDIM / 32;        // 24

    auto issue = [&](int s, int buf) {
        const int ko = s * 32;
        const uint32_t b = sbase + (uint32_t)buf * GT_BUF;
        cp_async16(b + so0,               Ah + gA0 + ko, a0ok);
        cp_async16(b + so1,               Ah + gA1 + ko, a1ok);
        cp_async16(b + GT_TILE + so0,     Al + gA0 + ko, a0ok);
        cp_async16(b + GT_TILE + so1,     Al + gA1 + ko, a1ok);
        cp_async16(b + 2 * GT_TILE + so0, Bh + gB0 + ko, true);
        cp_async16(b + 2 * GT_TILE + so1, Bh + gB1 + ko, true);
        cp_async16(b + 3 * GT_TILE + so0, Bl + gB0 + ko, true);
        cp_async16(b + 3 * GT_TILE + so1, Bl + gB1 + ko, true);
    };

    issue(0, 0); cp_commit();
    issue(1, 1); cp_commit();

    int buf = 0;
    for (int s = 0; s < NSTAGE; s++) {
        if (s == NSTAGE - 1) cp_wait<0>();   // drain: guarantee last stage landed
        else                 cp_wait<1>();
        __syncthreads();

        if (s + 2 < NSTAGE) {
            issue(s + 2, (s + 2) % 3);
            cp_commit();
        }

        const uint32_t tbase = sbase + (uint32_t)buf * GT_BUF;
#pragma unroll
        for (int kk2 = 0; kk2 < 2; kk2++) {
            uint32_t ah[4][4], al[4][4];
#pragma unroll
            for (int mi = 0; mi < 4; mi++) {
                ldsm4(ah[mi], tbase + offA[kk2][mi]);
                ldsm4(al[mi], tbase + GT_TILE + offA[kk2][mi]);
            }
#pragma unroll
            for (int nb = 0; nb < 2; nb++) {
                uint32_t bh[4], bl[4];
                ldsm4(bh, tbase + 2 * GT_TILE + offB[kk2][nb]);
                ldsm4(bl, tbase + 3 * GT_TILE + offB[kk2][nb]);
                // pass 0: Ah*Bh over all 8 accumulators
#pragma unroll
                for (int mi = 0; mi < 4; mi++)
#pragma unroll
                    for (int nsub = 0; nsub < 2; nsub++)
                        mma16816(acc[mi][nb * 2 + nsub], ah[mi],
                                 bh[nsub], bh[nsub + 2]);
                // pass 1: Ah*Bl
#pragma unroll
                for (int mi = 0; mi < 4; mi++)
#pragma unroll
                    for (int nsub = 0; nsub < 2; nsub++)
                        mma16816(acc[mi][nb * 2 + nsub], ah[mi],
                                 bl[nsub], bl[nsub + 2]);
                // pass 2: Al*Bh
#pragma unroll
                for (int mi = 0; mi < 4; mi++)
#pragma unroll
                    for (int nsub = 0; nsub < 2; nsub++)
                        mma16816(acc[mi][nb * 2 + nsub], al[mi],
                                 bh[nsub], bh[nsub + 2]);
            }
        }
        buf = (buf + 1) % 3;
    }

    // ---- epilogue ----
    const int erow = lane >> 2;
    const int ecol = (lane & 3) << 1;

    if (!ROPE) {
#pragma unroll
        for (int mi = 0; mi < 4; mi++) {
#pragma unroll
            for (int ni = 0; ni < 4; ni++) {
                int r = block_row + wm * 64 + mi * 16 + erow;
                int col = block_col + wn * 32 + ni * 8 + ecol;
                float2 bv = *(const float2*)(bias + col);
                if (r < M) {
                    float2 o = make_float2(acc[mi][ni][0] + bv.x,
                                           acc[mi][ni][1] + bv.y);
                    *(float2*)(C + (size_t)r * N + col) = o;
                }
                if (r + 8 < M) {
                    float2 o = make_float2(acc[mi][ni][2] + bv.x,
                                           acc[mi][ni][3] + bv.y);
                    *(float2*)(C + (size_t)(r + 8) * N + col) = o;
                }
            }
        }
    } else {
        // fused RoPE + bf16 hi/lo split + scatter to Q/K/V
        const int sec = block_col / CDIM;               // 0=Q,1=K,2=V (const/CTA)
        const int hbase = (block_col % CDIM) / DHEAD;
        __nv_bfloat16* dh = sec == 0 ? gQh : (sec == 1 ? gKh : gVh);
        __nv_bfloat16* dl = sec == 0 ? gQl : (sec == 1 ? gKl : gVl);
#pragma unroll
        for (int mi = 0; mi < 4; mi++) {
#pragma unroll
            for (int rp = 0; rp < 2; rp++) {
                int r = block_row + wm * 64 + mi * 16 + erow + rp * 8;
                if (r >= M) continue;
                int bidx = r / NTOK;
                int n = r - bidx * NTOK;
#pragma unroll
                for (int ni = 0; ni < 4; ni++) {
                    int lc = wn * 32 + ni * 8 + ecol;
                    int col = block_col + lc;
                    float v0 = acc[mi][ni][rp * 2 + 0] + bias[col];
                    float v1 = acc[mi][ni][rp * 2 + 1] + bias[col + 1];
                    int d = lc & 63;
                    int h = hbase + (lc >> 6);
                    if (sec < 2 && n > 0) {
                        float cc = cosb[(size_t)(n - 1) * 32 + (d >> 1)];
                        float ss = sinb[(size_t)(n - 1) * 32 + (d >> 1)];
                        float t0 = v0 * cc - v1 * ss;
                        float t1 = v0 * ss + v1 * cc;
                        v0 = t0; v1 = t1;
                    }
                    float h0 = __bfloat162float(__float2bfloat16_rn(v0));
                    float h1 = __bfloat162float(__float2bfloat16_rn(v1));
                    size_t o = ((size_t)(bidx * HEADS + h) * NTOK + n) * DHEAD + d;
                    *(uint32_t*)(dh + o) = pack_bf16x2(h0, h1);
                    *(uint32_t*)(dl + o) = pack_bf16x2(v0 - h0, v1 - h1);
                }
            }
        }
    }
}

// ============== Flash attention on HMMA, bf16x3, 128 q-rows/CTA =============
// 2-stage cp.async double buffer for K/V. smem 96KB; 2 CTAs/SM.
#define ASM_QH   0
#define ASM_QL   16384
#define ASM_KV0  32768
#define ASM_KVSZ 32768                 // KH+0, KL+8192, VH+16384, VL+24576
#define ASM_TOTAL 98304

__global__ __launch_bounds__(256, 2) void k_attn_mma() {
    extern __shared__ __align__(128) char asmem[];
    const uint32_t sb = smem_to_u32(asmem);
    const int tid = threadIdx.x;
    const int lane = tid & 31;
    const int wid = tid >> 5;
    const int bh = blockIdx.y;
    const int q0 = blockIdx.x * 128;
    const size_t gbase = (size_t)bh * NTOK * DHEAD;

    // ---- load Q tile (persistent) ----
#pragma unroll
    for (int i = 0; i < 4; i++) {
        int u = tid + (i << 8);
        int r = u >> 3, c = u & 7;
        uint32_t so = (uint32_t)(r * 128 + ((c ^ (r & 7)) << 4));
        uint4 zh = make_uint4(0, 0, 0, 0), zl = zh;
        if (q0 + r < NTOK) {
            size_t g = gbase + (size_t)(q0 + r) * DHEAD + c * 8;
            zh = *(const uint4*)(gQh + g);
            zl = *(const uint4*)(gQl + g);
        }
        *(uint4*)(asmem + ASM_QH + so) = zh;
        *(uint4*)(asmem + ASM_QL + so) = zl;
    }

    // ---- K/V async stage loader ----
    auto issueKV = [&](int kt) {
        const int k0 = kt * 64;
        const uint32_t base = sb + ASM_KV0 + (uint32_t)(kt & 1) * ASM_KVSZ;
#pragma unroll
        for (int i = 0; i < 2; i++) {
            int u = tid + (i << 8);
            int r = u >> 3, c = u & 7;
            uint32_t so = (uint32_t)(r * 128 + ((c ^ (r & 7)) << 4));
            bool ok = (k0 + r) < NTOK;
            int rr = ok ? (k0 + r) : (NTOK - 1);
            size_t g = gbase + (size_t)rr * DHEAD + c * 8;
            cp_async16(base + so,         gKh + g, ok);
            cp_async16(base + 8192 + so,  gKl + g, ok);
            cp_async16(base + 16384 + so, gVh + g, ok);
            cp_async16(base + 24576 + so, gVl + g, ok);
        }
    };

    const int m0 = wid * 16;
    const int alr = m0 + (lane & 15);
    const int akc = lane >> 4;
    uint32_t offQ[4];
#pragma unroll
    for (int k16 = 0; k16 < 4; k16++)
        offQ[k16] = (uint32_t)(alr * 128 + (((2 * k16 + akc) ^ (alr & 7)) << 4));

    float m_[2] = {-1e30f, -1e30f};
    float l_[2] = {0.f, 0.f};
    float o[8][4];
#pragma unroll
    for (int t = 0; t < 8; t++)
#pragma unroll
        for (int j = 0; j < 4; j++) o[t][j] = 0.f;

    const float scale = 0.125f;

    issueKV(0); cp_commit();

    for (int kt = 0; kt < 10; kt++) {
        const int k0 = kt * 64;
        cp_wait<0>();          // stage kt landed
        __syncthreads();       // visible + all warps done with stage kt-1 buffer

        if (kt + 1 < 10) {     // prefetch overlaps compute of stage kt
            issueKV(kt + 1);
            cp_commit();
        }

        const uint32_t kvb = sb + ASM_KV0 + (uint32_t)(kt & 1) * ASM_KVSZ;

        // ---- S = Q @ K^T (x3 split, pass-ordered) ----
        float s[8][4];
#pragma unroll
        for (int t = 0; t < 8; t++)
#pragma unroll
            for (int j = 0; j < 4; j++) s[t][j] = 0.f;

#pragma unroll
        for (int k16 = 0; k16 < 4; k16++) {
            uint32_t qh[4], ql[4];
            ldsm4(qh, sb + ASM_QH + offQ[k16]);
            ldsm4(ql, sb + ASM_QL + offQ[k16]);
#pragma unroll
            for (int nb = 0; nb < 4; nb++) {
                int krow = nb * 16 + (lane & 15);
                uint32_t off = (uint32_t)(krow * 128 +
                                (((2 * k16 + akc) ^ (krow & 7)) << 4));
                uint32_t kh[4], kl[4];
                ldsm4(kh, kvb + off);
                ldsm4(kl, kvb + 8192 + off);
                // pass-ordered: both accumulators per product
#pragma unroll
                for (int nsub = 0; nsub < 2; nsub++)
                    mma16816(s[nb * 2 + nsub], qh, kh[nsub], kh[nsub + 2]);
#pragma unroll
                for (int nsub = 0; nsub < 2; nsub++)
                    mma16816(s[nb * 2 + nsub], qh, kl[nsub], kl[nsub + 2]);
#pragma unroll
                for (int nsub = 0; nsub < 2; nsub++)
                    mma16816(s[nb * 2 + nsub], ql, kh[nsub], kh[nsub + 2]);
            }
        }

        const bool lastt = (k0 + 64 > NTOK);
        float fi[2];
#pragma unroll
        for (int j = 0; j < 2; j++) {
            float rm = -1e30f;
#pragma unroll
            for (int t = 0; t < 8; t++) {
#pragma unroll
                for (int c = 0; c < 2; c++) {
                    float v = s[t][j * 2 + c] * scale;
                    if (lastt) {
                        int col = k0 + t * 8 + ((lane & 3) << 1) + c;
                        if (col >= NTOK) v = -1e30f;
                    }
                    s[t][j * 2 + c] = v;
                    rm = fmaxf(rm, v);
                }
            }
            rm = fmaxf(rm, __shfl_xor_sync(0xffffffffu, rm, 1));
            rm = fmaxf(rm, __shfl_xor_sync(0xffffffffu, rm, 2));
            float mn = fmaxf(m_[j], rm);
            fi[j] = __expf(m_[j] - mn);
            m_[j] = mn;
            float rs = 0.f;
#pragma unroll
            for (int t = 0; t < 8; t++) {
#pragma unroll
                for (int c = 0; c < 2; c++) {
                    float p = __expf(s[t][j * 2 + c] - mn);
                    s[t][j * 2 + c] = p;
                    rs += p;
                }
            }
            rs += __shfl_xor_sync(0xffffffffu, rs, 1);
            rs += __shfl_xor_sync(0xffffffffu, rs, 2);
            l_[j] = l_[j] * fi[j] + rs;
        }
#pragma unroll
        for (int t = 0; t < 8; t++) {
            o[t][0] *= fi[0]; o[t][1] *= fi[0];
            o[t][2] *= fi[1]; o[t][3] *= fi[1];
        }

        // ---- O += P @ V (x3 split, pass-ordered) ----
#pragma unroll
        for (int t2 = 0; t2 < 4; t2++) {
            uint32_t ph[4], pl[4];
#pragma unroll
            for (int idx = 0; idx < 4; idx++) {
                int t = 2 * t2 + (idx >> 1);
                int j = idx & 1;
                float x0 = s[t][j * 2 + 0];
                float x1 = s[t][j * 2 + 1];
                float h0 = __bfloat162float(__float2bfloat16_rn(x0));
                float h1 = __bfloat162float(__float2bfloat16_rn(x1));
                ph[idx] = pack_bf16x2(h0, h1);
                pl[idx] = pack_bf16x2(x0 - h0, x1 - h1);
            }
            const int vm = lane >> 3;
            const int vk = t2 * 16 + ((vm & 1) << 3) + (lane & 7);
#pragma unroll
            for (int nb = 0; nb < 4; nb++) {
                int vc = nb * 2 + (vm >> 1);
                uint32_t off = (uint32_t)(vk * 128 + ((vc ^ (vk & 7)) << 4));
                uint32_t vh[4], vl[4];
                ldsm4t(vh, kvb + 16384 + off);
                ldsm4t(vl, kvb + 24576 + off);
                // pass-ordered: alternate the two output accumulators
                mma16816(o[nb * 2 + 0], ph, vh[0], vh[1]);
                mma16816(o[nb * 2 + 1], ph, vh[2], vh[3]);
                mma16816(o[nb * 2 + 0], ph, vl[0], vl[1]);
                mma16816(o[nb * 2 + 1], ph, vl[2], vl[3]);
                mma16816(o[nb * 2 + 0], pl, vh[0], vh[1]);
                mma16816(o[nb * 2 + 1], pl, vh[2], vh[3]);
            }
        }
    }

    const int b = bh / HEADS;
    const int h = bh % HEADS;
#pragma unroll
    for (int j = 0; j < 2; j++) {
        int n = q0 + m0 + (lane >> 2) + j * 8;
        if (n < NTOK) {
            float inv = 1.f / l_[j];
            size_t gr = (size_t)(b * NTOK + n) * CDIM + h * DHEAD;
#pragma unroll
            for (int t = 0; t < 8; t++) {
                int col = t * 8 + ((lane & 3) << 1);
                float x0 = o[t][j * 2 + 0] * inv;
                float x1 = o[t][j * 2 + 1] * inv;
                float h0 = __bfloat162float(__float2bfloat16_rn(x0));
                float h1 = __bfloat162float(__float2bfloat16_rn(x1));
                *(uint32_t*)(gCh + gr + col) = pack_bf16x2(h0, h1);
                *(uint32_t*)(gCl + gr + col) = pack_bf16x2(x0 - h0, x1 - h1);
            }
        }
    }
}

// ================================ launch ====================================
extern "C" void kernel_launch(void* const* d_in, const int* in_sizes, int n_in,
                              void* d_out, int out_size) {
    const float* x      = (const float*)d_in[0];
    const float* cosb   = (const float*)d_in[1];
    const float* sinb   = (const float*)d_in[2];
    const float* w_qkv  = (const float*)d_in[3];
    const float* b_qkv  = (const float*)d_in[4];
    const float* w_proj = (const float*)d_in[5];
    const float* b_proj = (const float*)d_in[6];
    float* out = (float*)d_out;

    cudaFuncSetAttribute(k_gemm_mma<true>,
                         cudaFuncAttributeMaxDynamicSharedMemorySize, GT_SMEM);
    cudaFuncSetAttribute(k_gemm_mma<false>,
                         cudaFuncAttributeMaxDynamicSharedMemorySize, GT_SMEM);
    cudaFuncSetAttribute(k_attn_mma,
                         cudaFuncAttributeMaxDynamicSharedMemorySize, ASM_TOTAL);

    __nv_bfloat16 *pAh, *pAl, *pCh, *pCl, *pWqh, *pWql, *pWph, *pWpl;
    cudaGetSymbolAddress((void**)&pAh,  gAh);
    cudaGetSymbolAddress((void**)&pAl,  gAl);
    cudaGetSymbolAddress((void**)&pCh,  gCh);
    cudaGetSymbolAddress((void**)&pCl,  gCl);
    cudaGetSymbolAddress((void**)&pWqh, gWqh);
    cudaGetSymbolAddress((void**)&pWql, gWql);
    cudaGetSymbolAddress((void**)&pWph, gWph);
    cudaGetSymbolAddress((void**)&pWpl, gWpl);

    // 0) fused operand preparation
    k_prep<<<NB_X + NB_WQ + NB_WP, 256>>>(x, w_qkv, w_proj);

    // 1) QKV GEMM + fused RoPE/split (HMMA bf16x3, cp.async pipeline)
    {
        dim3 grid(QKVCOLS / 128, (MROWS + 127) / 128);
        k_gemm_mma<true><<<grid, 256, GT_SMEM>>>(pAh, pAl, pWqh, pWql, b_qkv,
                                                 nullptr, MROWS, QKVCOLS,
                                                 cosb, sinb);
    }
    // 2) attention (HMMA bf16x3, double-buffered K/V) — writes gCh/gCl
    {
        dim3 grid((NTOK + 127) / 128, BHTOT);
        k_attn_mma<<<grid, 256, ASM_TOTAL>>>();
    }
    // 3) output projection (HMMA bf16x3, cp.async pipeline)
    {
        dim3 grid(CDIM / 128, (MROWS + 127) / 128);
        k_gemm_mma<false><<<grid, 256, GT_SMEM>>>(pCh, pCl, pWph, pWpl, b_proj,
                                                  out, MROWS, CDIM,
                                                  nullptr, nullptr);
    }
}

// round 17
// speedup vs baseline: 1.5029x; 1.3783x over previous
#include <cuda_runtime.h>
#include <cuda_fp16.h>
#include <cstdint>
#include <cstddef>

// Problem constants
#define BATCH   16
#define NTOK    577
#define CDIM    768
#define HEADS   12
#define DHEAD   64
#define MROWS   (BATCH * NTOK)          // 9232
#define QKVCOLS (3 * CDIM)              // 2304
#define BHTOT   (BATCH * HEADS)         // 192

// ===================== helpers ==============================================
__device__ __forceinline__ uint32_t smem_to_u32(const void* smem_ptr) {
    uint32_t addr;
    asm("{ .reg .u64 tmp; cvta.to.shared.u64 tmp, %1; cvt.u32.u64 %0, tmp; }"
        : "=r"(addr) : "l"(smem_ptr));
    return addr;
}

__device__ __forceinline__ void ldsm4(uint32_t* r, uint32_t addr) {
    asm volatile("ldmatrix.sync.aligned.m8n8.x4.shared.b16 {%0,%1,%2,%3}, [%4];"
                 : "=r"(r[0]), "=r"(r[1]), "=r"(r[2]), "=r"(r[3]) : "r"(addr));
}

__device__ __forceinline__ void ldsm4t(uint32_t* r, uint32_t addr) {
    asm volatile("ldmatrix.sync.aligned.m8n8.x4.trans.shared.b16 {%0,%1,%2,%3}, [%4];"
                 : "=r"(r[0]), "=r"(r[1]), "=r"(r[2]), "=r"(r[3]) : "r"(addr));
}

// fp16 HMMA, fp32 accumulate
__device__ __forceinline__ void mma16816(float* c, const uint32_t* a,
                                         uint32_t b0, uint32_t b1) {
    asm volatile(
        "mma.sync.aligned.m16n8k16.row.col.f32.f16.f16.f32 "
        "{%0,%1,%2,%3}, {%4,%5,%6,%7}, {%8,%9}, {%0,%1,%2,%3};"
        : "+f"(c[0]), "+f"(c[1]), "+f"(c[2]), "+f"(c[3])
        : "r"(a[0]), "r"(a[1]), "r"(a[2]), "r"(a[3]), "r"(b0), "r"(b1));
}

// pack(lo, hi) -> f16x2 register (lo in lower 16 bits)
__device__ __forceinline__ uint32_t pack_f16x2(float lo, float hi) {
    uint32_t r;
    asm("cvt.rn.f16x2.f32 %0, %1, %2;" : "=r"(r) : "f"(hi), "f"(lo));
    return r;
}

// 16B async copy; pred=false => zero-fill (reads 0 bytes)
__device__ __forceinline__ void cp_async16(uint32_t dst, const void* src, bool pred) {
    int sz = pred ? 16 : 0;
    asm volatile("cp.async.cg.shared.global [%0], [%1], 16, %2;"
                 :: "r"(dst), "l"(src), "r"(sz) : "memory");
}
__device__ __forceinline__ void cp_commit() {
    asm volatile("cp.async.commit_group;" ::: "memory");
}
template <int N>
__device__ __forceinline__ void cp_wait() {
    asm volatile("cp.async.wait_group %0;" :: "n"(N) : "memory");
}

// ---------------- scratch (no allocations allowed -> device globals) --------
// fp16 operands: A-side split hi/lo (22-bit effective), B-side single fp16.
__device__ __half gAh[(size_t)MROWS * CDIM];           // x split hi
__device__ __half gAl[(size_t)MROWS * CDIM];           // x split lo
__device__ __half gCh[(size_t)MROWS * CDIM];           // attn-out split hi
__device__ __half gCl[(size_t)MROWS * CDIM];           // attn-out split lo
__device__ __half gWq[(size_t)QKVCOLS * CDIM];         // w_qkv^T fp16
__device__ __half gWp[(size_t)CDIM * CDIM];            // w_proj^T fp16

// Q split hi/lo; K,V single fp16. (B*H, N, D)
__device__ __half gQh[(size_t)BHTOT * NTOK * DHEAD];
__device__ __half gQl[(size_t)BHTOT * NTOK * DHEAD];
__device__ __half gK [(size_t)BHTOT * NTOK * DHEAD];
__device__ __half gV [(size_t)BHTOT * NTOK * DHEAD];

// =============== fused operand prep (split x + transpose weights) ===========
#define NB_X  ((MROWS * CDIM / 4 + 1023) / 1024)         // 4 float4 per thread
#define NB_WQ ((QKVCOLS / 32) * (CDIM / 32))             // 1728
#define NB_WP ((CDIM / 32) * (CDIM / 32))                // 576

__device__ __forceinline__ void wsplit_body(const float* __restrict__ w,
                                            __half* __restrict__ oh,
                                            int K, int N, int bx, int by,
                                            int tid, float (*t)[33]) {
    int n0 = bx * 32, k0 = by * 32;
    int tx = tid & 31, ty = tid >> 5;
#pragma unroll
    for (int j = 0; j < 32; j += 8)
        t[ty + j][tx] = w[(size_t)(k0 + ty + j) * N + n0 + tx];
    __syncthreads();
#pragma unroll
    for (int j = 0; j < 32; j += 8) {
        float v = t[tx][ty + j];
        int n = n0 + ty + j, k = k0 + tx;
        oh[(size_t)n * K + k] = __float2half_rn(v);
    }
}

__global__ __launch_bounds__(256) void k_prep(const float* __restrict__ x,
                                              const float* __restrict__ w_qkv,
                                              const float* __restrict__ w_proj) {
    __shared__ float t[32][33];
    const int b = blockIdx.x;
    const int tid = threadIdx.x;
    if (b < NB_X) {
        const int n4 = MROWS * CDIM / 4;
#pragma unroll
        for (int j = 0; j < 4; j++) {
            int i = b * 1024 + j * 256 + tid;
            if (i < n4) {
                float4 v = ((const float4*)x)[i];
                float f[4] = {v.x, v.y, v.z, v.w};
                __align__(8) __half h[4];
                __align__(8) __half l[4];
#pragma unroll
                for (int q = 0; q < 4; q++) {
                    h[q] = __float2half_rn(f[q]);
                    l[q] = __float2half_rn(f[q] - __half2float(h[q]));
                }
                *(uint2*)(gAh + 4 * (size_t)i) = *(uint2*)h;
                *(uint2*)(gAl + 4 * (size_t)i) = *(uint2*)l;
            }
        }
    } else if (b < NB_X + NB_WQ) {
        int bb = b - NB_X;
        wsplit_body(w_qkv, gWq, CDIM, QKVCOLS,
                    bb % (QKVCOLS / 32), bb / (QKVCOLS / 32), tid, t);
    } else {
        int bb = b - NB_X - NB_WQ;
        wsplit_body(w_proj, gWp, CDIM, CDIM,
                    bb % (CDIM / 32), bb / (CDIM / 32), tid, t);
    }
}

// =================== HMMA fp16x2 GEMM: C = A@B + bias =======================
// A split hi/lo fp16 (2 passes), B single fp16. 3-stage cp.async; 2 CTAs/SM.
// Tile 128x128, BK=32, 8 warps (2x4). Pass-ordered MMA scheduling.
#define GT_TILE 8192                    // 128 x 32 fp16
#define GT_BUF  (3 * GT_TILE)           // 24KB / stage (Ah,Al,B)
#define GT_SMEM (3 * GT_BUF)            // 72KB, 3 stages

template <bool ROPE>
__global__ __launch_bounds__(256, 2) void k_gemm_mma(
    const __half* __restrict__ Ah, const __half* __restrict__ Al,
    const __half* __restrict__ Bm,
    const float* __restrict__ bias, float* __restrict__ C, int M, int N,
    const float* __restrict__ cosb, const float* __restrict__ sinb) {
    extern __shared__ __align__(128) char smem[];
    const uint32_t sbase = smem_to_u32(smem);

    const int tid  = threadIdx.x;
    const int lane = tid & 31;
    const int wid  = tid >> 5;
    const int wm   = wid >> 2;
    const int wn   = wid & 3;
    const int block_row = blockIdx.y * 128;
    const int block_col = blockIdx.x * 128;

    // global->smem chunk mapping (2 chunks per thread per tile)
    const int u0 = tid, u1 = tid + 256;
    const int r0 = u0 >> 2, c0 = u0 & 3;
    const int r1 = u1 >> 2, c1 = u1 & 3;
    const uint32_t so0 = (uint32_t)(r0 * 64 + ((c0 ^ ((r0 >> 1) & 3)) << 4));
    const uint32_t so1 = (uint32_t)(r1 * 64 + ((c1 ^ ((r1 >> 1) & 3)) << 4));
    const bool a0ok = (block_row + r0) < M;
    const bool a1ok = (block_row + r1) < M;
    const int ar0 = a0ok ? (block_row + r0) : (M - 1);
    const int ar1 = a1ok ? (block_row + r1) : (M - 1);
    const size_t gA0 = (size_t)ar0 * CDIM + c0 * 8;
    const size_t gA1 = (size_t)ar1 * CDIM + c1 * 8;
    const size_t gB0 = (size_t)(block_col + r0) * CDIM + c0 * 8;
    const size_t gB1 = (size_t)(block_col + r1) * CDIM + c1 * 8;

    // ldmatrix source offsets (loop invariant)
    const int lrow = lane & 15;
    const int lkc  = lane >> 4;
    uint32_t offA[2][4], offB[2][2];
#pragma unroll
    for (int kk2 = 0; kk2 < 2; kk2++) {
        int cc = kk2 * 2 + lkc;
#pragma unroll
        for (int mi = 0; mi < 4; mi++) {
            int rr = wm * 64 + mi * 16 + lrow;
            offA[kk2][mi] = (uint32_t)(rr * 64 + ((cc ^ ((rr >> 1) & 3)) << 4));
        }
#pragma unroll
        for (int nb = 0; nb < 2; nb++) {
            int rr = wn * 32 + nb * 16 + lrow;
            offB[kk2][nb] = (uint32_t)(rr * 64 + ((cc ^ ((rr >> 1) & 3)) << 4));
        }
    }

    float acc[4][4][4];
#pragma unroll
    for (int mi = 0; mi < 4; mi++)
#pragma unroll
        for (int ni = 0; ni < 4; ni++)
#pragma unroll
            for (int j = 0; j < 4; j++) acc[mi][ni][j] = 0.f;

    const int NSTAGE = CDIM / 32;        // 24

    auto issue = [&](int s, int buf) {
        const int ko = s * 32;
        const uint32_t b = sbase + (uint32_t)buf * GT_BUF;
        cp_async16(b + so0,               Ah + gA0 + ko, a0ok);
        cp_async16(b + so1,               Ah + gA1 + ko, a1ok);
        cp_async16(b + GT_TILE + so0,     Al + gA0 + ko, a0ok);
        cp_async16(b + GT_TILE + so1,     Al + gA1 + ko, a1ok);
        cp_async16(b + 2 * GT_TILE + so0, Bm + gB0 + ko, true);
        cp_async16(b + 2 * GT_TILE + so1, Bm + gB1 + ko, true);
    };

    issue(0, 0); cp_commit();
    issue(1, 1); cp_commit();

    int buf = 0;
    for (int s = 0; s < NSTAGE; s++) {
        if (s == NSTAGE - 1) cp_wait<0>();   // drain: last stage landed
        else                 cp_wait<1>();
        __syncthreads();

        if (s + 2 < NSTAGE) {
            issue(s + 2, (s + 2) % 3);
            cp_commit();
        }

        const uint32_t tbase = sbase + (uint32_t)buf * GT_BUF;
#pragma unroll
        for (int kk2 = 0; kk2 < 2; kk2++) {
            uint32_t ah[4][4], al[4][4];
#pragma unroll
            for (int mi = 0; mi < 4; mi++) {
                ldsm4(ah[mi], tbase + offA[kk2][mi]);
                ldsm4(al[mi], tbase + GT_TILE + offA[kk2][mi]);
            }
#pragma unroll
            for (int nb = 0; nb < 2; nb++) {
                uint32_t bh[4];
                ldsm4(bh, tbase + 2 * GT_TILE + offB[kk2][nb]);
                // pass 0: Ah*B over all 8 accumulators
#pragma unroll
                for (int mi = 0; mi < 4; mi++)
#pragma unroll
                    for (int nsub = 0; nsub < 2; nsub++)
                        mma16816(acc[mi][nb * 2 + nsub], ah[mi],
                                 bh[nsub], bh[nsub + 2]);
                // pass 1: Al*B
#pragma unroll
                for (int mi = 0; mi < 4; mi++)
#pragma unroll
                    for (int nsub = 0; nsub < 2; nsub++)
                        mma16816(acc[mi][nb * 2 + nsub], al[mi],
                                 bh[nsub], bh[nsub + 2]);
            }
        }
        buf = (buf + 1) % 3;
    }

    // ---- epilogue ----
    const int erow = lane >> 2;
    const int ecol = (lane & 3) << 1;

    if (!ROPE) {
#pragma unroll
        for (int mi = 0; mi < 4; mi++) {
#pragma unroll
            for (int ni = 0; ni < 4; ni++) {
                int r = block_row + wm * 64 + mi * 16 + erow;
                int col = block_col + wn * 32 + ni * 8 + ecol;
                float2 bv = *(const float2*)(bias + col);
                if (r < M) {
                    float2 o = make_float2(acc[mi][ni][0] + bv.x,
                                           acc[mi][ni][1] + bv.y);
                    *(float2*)(C + (size_t)r * N + col) = o;
                }
                if (r + 8 < M) {
                    float2 o = make_float2(acc[mi][ni][2] + bv.x,
                                           acc[mi][ni][3] + bv.y);
                    *(float2*)(C + (size_t)(r + 8) * N + col) = o;
                }
            }
        }
    } else {
        // fused RoPE + fp16 split/round + scatter to Q(split)/K/V(single)
        const int sec = block_col / CDIM;               // 0=Q,1=K,2=V (const/CTA)
        const int hbase = (block_col % CDIM) / DHEAD;
#pragma unroll
        for (int mi = 0; mi < 4; mi++) {
#pragma unroll
            for (int rp = 0; rp < 2; rp++) {
                int r = block_row + wm * 64 + mi * 16 + erow + rp * 8;
                if (r >= M) continue;
                int bidx = r / NTOK;
                int n = r - bidx * NTOK;
#pragma unroll
                for (int ni = 0; ni < 4; ni++) {
                    int lc = wn * 32 + ni * 8 + ecol;
                    int col = block_col + lc;
                    float v0 = acc[mi][ni][rp * 2 + 0] + bias[col];
                    float v1 = acc[mi][ni][rp * 2 + 1] + bias[col + 1];
                    int d = lc & 63;
                    int h = hbase + (lc >> 6);
                    if (sec < 2 && n > 0) {
                        float cc = cosb[(size_t)(n - 1) * 32 + (d >> 1)];
                        float ss = sinb[(size_t)(n - 1) * 32 + (d >> 1)];
                        float t0 = v0 * cc - v1 * ss;
                        float t1 = v0 * ss + v1 * cc;
                        v0 = t0; v1 = t1;
                    }
                    size_t o = ((size_t)(bidx * HEADS + h) * NTOK + n) * DHEAD + d;
                    if (sec == 0) {
                        float h0 = __half2float(__float2half_rn(v0));
                        float h1 = __half2float(__float2half_rn(v1));
                        *(uint32_t*)(gQh + o) = pack_f16x2(h0, h1);
                        *(uint32_t*)(gQl + o) = pack_f16x2(v0 - h0, v1 - h1);
                    } else if (sec == 1) {
                        *(uint32_t*)(gK + o) = pack_f16x2(v0, v1);
                    } else {
                        *(uint32_t*)(gV + o) = pack_f16x2(v0, v1);
                    }
                }
            }
        }
    }
}

// ============== Flash attention on HMMA fp16x2, 128 q-rows/CTA ==============
// Q split hi/lo (2 passes), K/V single fp16. 2-stage cp.async K/V double buffer.
#define ASM_QH   0
#define ASM_QL   16384
#define ASM_KV0  32768
#define ASM_KVSZ 16384                 // K at +0, V at +8192
#define ASM_TOTAL 65536

__global__ __launch_bounds__(256, 2) void k_attn_mma() {
    extern __shared__ __align__(128) char asmem[];
    const uint32_t sb = smem_to_u32(asmem);
    const int tid = threadIdx.x;
    const int lane = tid & 31;
    const int wid = tid >> 5;
    const int bh = blockIdx.y;
    const int q0 = blockIdx.x * 128;
    const size_t gbase = (size_t)bh * NTOK * DHEAD;

    // ---- load Q tile (persistent) ----
#pragma unroll
    for (int i = 0; i < 4; i++) {
        int u = tid + (i << 8);
        int r = u >> 3, c = u & 7;
        uint32_t so = (uint32_t)(r * 128 + ((c ^ (r & 7)) << 4));
        uint4 zh = make_uint4(0, 0, 0, 0), zl = zh;
        if (q0 + r < NTOK) {
            size_t g = gbase + (size_t)(q0 + r) * DHEAD + c * 8;
            zh = *(const uint4*)(gQh + g);
            zl = *(const uint4*)(gQl + g);
        }
        *(uint4*)(asmem + ASM_QH + so) = zh;
        *(uint4*)(asmem + ASM_QL + so) = zl;
    }

    // ---- K/V async stage loader ----
    auto issueKV = [&](int kt) {
        const int k0 = kt * 64;
        const uint32_t base = sb + ASM_KV0 + (uint32_t)(kt & 1) * ASM_KVSZ;
#pragma unroll
        for (int i = 0; i < 2; i++) {
            int u = tid + (i << 8);
            int r = u >> 3, c = u & 7;
            uint32_t so = (uint32_t)(r * 128 + ((c ^ (r & 7)) << 4));
            bool ok = (k0 + r) < NTOK;
            int rr = ok ? (k0 + r) : (NTOK - 1);
            size_t g = gbase + (size_t)rr * DHEAD + c * 8;
            cp_async16(base + so,        gK + g, ok);
            cp_async16(base + 8192 + so, gV + g, ok);
        }
    };

    const int m0 = wid * 16;
    const int alr = m0 + (lane & 15);
    const int akc = lane >> 4;
    uint32_t offQ[4];
#pragma unroll
    for (int k16 = 0; k16 < 4; k16++)
        offQ[k16] = (uint32_t)(alr * 128 + (((2 * k16 + akc) ^ (alr & 7)) << 4));

    float m_[2] = {-1e30f, -1e30f};
    float l_[2] = {0.f, 0.f};
    float o[8][4];
#pragma unroll
    for (int t = 0; t < 8; t++)
#pragma unroll
        for (int j = 0; j < 4; j++) o[t][j] = 0.f;

    const float scale = 0.125f;

    issueKV(0); cp_commit();

    for (int kt = 0; kt < 10; kt++) {
        const int k0 = kt * 64;
        cp_wait<0>();          // stage kt landed
        __syncthreads();       // visible + all warps done with stage kt-1 buffer

        if (kt + 1 < 10) {     // prefetch overlaps compute of stage kt
            issueKV(kt + 1);
            cp_commit();
        }

        const uint32_t kvb = sb + ASM_KV0 + (uint32_t)(kt & 1) * ASM_KVSZ;

        // ---- S = Q @ K^T (Qh + Ql passes) ----
        float s[8][4];
#pragma unroll
        for (int t = 0; t < 8; t++)
#pragma unroll
            for (int j = 0; j < 4; j++) s[t][j] = 0.f;

#pragma unroll
        for (int k16 = 0; k16 < 4; k16++) {
            uint32_t qh[4], ql[4];
            ldsm4(qh, sb + ASM_QH + offQ[k16]);
            ldsm4(ql, sb + ASM_QL + offQ[k16]);
#pragma unroll
            for (int nb = 0; nb < 4; nb++) {
                int krow = nb * 16 + (lane & 15);
                uint32_t off = (uint32_t)(krow * 128 +
                                (((2 * k16 + akc) ^ (krow & 7)) << 4));
                uint32_t kh[4];
                ldsm4(kh, kvb + off);
#pragma unroll
                for (int nsub = 0; nsub < 2; nsub++)
                    mma16816(s[nb * 2 + nsub], qh, kh[nsub], kh[nsub + 2]);
#pragma unroll
                for (int nsub = 0; nsub < 2; nsub++)
                    mma16816(s[nb * 2 + nsub], ql, kh[nsub], kh[nsub + 2]);
            }
        }

        const bool lastt = (k0 + 64 > NTOK);
        float fi[2];
#pragma unroll
        for (int j = 0; j < 2; j++) {
            float rm = -1e30f;
#pragma unroll
            for (int t = 0; t < 8; t++) {
#pragma unroll
                for (int c = 0; c < 2; c++) {
                    float v = s[t][j * 2 + c] * scale;
                    if (lastt) {
                        int col = k0 + t * 8 + ((lane & 3) << 1) + c;
                        if (col >= NTOK) v = -1e30f;
                    }
                    s[t][j * 2 + c] = v;
                    rm = fmaxf(rm, v);
                }
            }
            rm = fmaxf(rm, __shfl_xor_sync(0xffffffffu, rm, 1));
            rm = fmaxf(rm, __shfl_xor_sync(0xffffffffu, rm, 2));
            float mn = fmaxf(m_[j], rm);
            fi[j] = __expf(m_[j] - mn);
            m_[j] = mn;
            float rs = 0.f;
#pragma unroll
            for (int t = 0; t < 8; t++) {
#pragma unroll
                for (int c = 0; c < 2; c++) {
                    float p = __expf(s[t][j * 2 + c] - mn);
                    s[t][j * 2 + c] = p;
                    rs += p;
                }
            }
            rs += __shfl_xor_sync(0xffffffffu, rs, 1);
            rs += __shfl_xor_sync(0xffffffffu, rs, 2);
            l_[j] = l_[j] * fi[j] + rs;
        }
#pragma unroll
        for (int t = 0; t < 8; t++) {
            o[t][0] *= fi[0]; o[t][1] *= fi[0];
            o[t][2] *= fi[1]; o[t][3] *= fi[1];
        }

        // ---- O += P @ V (Ph + Pl passes, V single) ----
#pragma unroll
        for (int t2 = 0; t2 < 4; t2++) {
            uint32_t ph[4], pl[4];
#pragma unroll
            for (int idx = 0; idx < 4; idx++) {
                int t = 2 * t2 + (idx >> 1);
                int j = idx & 1;
                float x0 = s[t][j * 2 + 0];
                float x1 = s[t][j * 2 + 1];
                float h0 = __half2float(__float2half_rn(x0));
                float h1 = __half2float(__float2half_rn(x1));
                ph[idx] = pack_f16x2(h0, h1);
                pl[idx] = pack_f16x2(x0 - h0, x1 - h1);
            }
            const int vm = lane >> 3;
            const int vk = t2 * 16 + ((vm & 1) << 3) + (lane & 7);
#pragma unroll
            for (int nb = 0; nb < 4; nb++) {
                int vc = nb * 2 + (vm >> 1);
                uint32_t off = (uint32_t)(vk * 128 + ((vc ^ (vk & 7)) << 4));
                uint32_t vh[4];
                ldsm4t(vh, kvb + 8192 + off);
                mma16816(o[nb * 2 + 0], ph, vh[0], vh[1]);
                mma16816(o[nb * 2 + 1], ph, vh[2], vh[3]);
                mma16816(o[nb * 2 + 0], pl, vh[0], vh[1]);
                mma16816(o[nb * 2 + 1], pl, vh[2], vh[3]);
            }
        }
    }

    const int b = bh / HEADS;
    const int h = bh % HEADS;
#pragma unroll
    for (int j = 0; j < 2; j++) {
        int n = q0 + m0 + (lane >> 2) + j * 8;
        if (n < NTOK) {
            float inv = 1.f / l_[j];
            size_t gr = (size_t)(b * NTOK + n) * CDIM + h * DHEAD;
#pragma unroll
            for (int t = 0; t < 8; t++) {
                int col = t * 8 + ((lane & 3) << 1);
                float x0 = o[t][j * 2 + 0] * inv;
                float x1 = o[t][j * 2 + 1] * inv;
                float h0 = __half2float(__float2half_rn(x0));
                float h1 = __half2float(__float2half_rn(x1));
                *(uint32_t*)(gCh + gr + col) = pack_f16x2(h0, h1);
                *(uint32_t*)(gCl + gr + col) = pack_f16x2(x0 - h0, x1 - h1);
            }
        }
    }
}

// ================================ launch ====================================
extern "C" void kernel_launch(void* const* d_in, const int* in_sizes, int n_in,
                              void* d_out, int out_size) {
    const float* x      = (const float*)d_in[0];
    const float* cosb   = (const float*)d_in[1];
    const float* sinb   = (const float*)d_in[2];
    const float* w_qkv  = (const float*)d_in[3];
    const float* b_qkv  = (const float*)d_in[4];
    const float* w_proj = (const float*)d_in[5];
    const float* b_proj = (const float*)d_in[6];
    float* out = (float*)d_out;

    cudaFuncSetAttribute(k_gemm_mma<true>,
                         cudaFuncAttributeMaxDynamicSharedMemorySize, GT_SMEM);
    cudaFuncSetAttribute(k_gemm_mma<false>,
                         cudaFuncAttributeMaxDynamicSharedMemorySize, GT_SMEM);
    cudaFuncSetAttribute(k_attn_mma,
                         cudaFuncAttributeMaxDynamicSharedMemorySize, ASM_TOTAL);

    __half *pAh, *pAl, *pCh, *pCl, *pWq, *pWp;
    cudaGetSymbolAddress((void**)&pAh, gAh);
    cudaGetSymbolAddress((void**)&pAl, gAl);
    cudaGetSymbolAddress((void**)&pCh, gCh);
    cudaGetSymbolAddress((void**)&pCl, gCl);
    cudaGetSymbolAddress((void**)&pWq, gWq);
    cudaGetSymbolAddress((void**)&pWp, gWp);

    // 0) fused operand preparation
    k_prep<<<NB_X + NB_WQ + NB_WP, 256>>>(x, w_qkv, w_proj);

    // 1) QKV GEMM + fused RoPE/split (HMMA fp16x2, cp.async pipeline)
    {
        dim3 grid(QKVCOLS / 128, (MROWS + 127) / 128);
        k_gemm_mma<true><<<grid, 256, GT_SMEM>>>(pAh, pAl, pWq, b_qkv,
                                                 nullptr, MROWS, QKVCOLS,
                                                 cosb, sinb);
    }
    // 2) attention (HMMA fp16x2, double-buffered K/V) — writes gCh/gCl
    {
        dim3 grid((NTOK + 127) / 128, BHTOT);
        k_attn_mma<<<grid, 256, ASM_TOTAL>>>();
    }
    // 3) output projection (HMMA fp16x2, cp.async pipeline)
    {
        dim3 grid(CDIM / 128, (MROWS + 127) / 128);
        k_gemm_mma<false><<<grid, 256, GT_SMEM>>>(pCh, pCl, pWp, b_proj,
                                                  out, MROWS, CDIM,
                                                  nullptr, nullptr);
    }
}